// round 1
// baseline (speedup 1.0000x reference)
#include <cuda_runtime.h>
#include <math.h>

#define BB 4
#define CC 512
#define TT 1024
#define HH 8
#define HDD 64
#define FF 2048
#define LL 4
#define WW 4
#define RNUM 9
#define ASTRIDE 68

// ---------------- scratch (no allocations allowed) ----------------
__device__ float g_x[BB*CC*TT];
__device__ float g_q[BB*CC*TT];
__device__ float g_k[BB*CC*TT];
__device__ float g_v[BB*CC*TT];
__device__ float g_o[BB*CC*TT];
__device__ float g_t[BB*CC*TT];
__device__ float g_h[BB*FF*TT];

// ---------------- batched GEMM: out[b][m][n] = sum_k W[m][k] X[b][k][n] (+bias, epilogue) ----
// tile 128x128x16, 256 threads, 8x8 micro-tile. M,N,K all multiples of tile dims here.
template<int RELU, int MASK_IN, int MASK_OUT, int DO_SCALE>
__global__ void __launch_bounds__(256) gemm_kernel(
    const float* __restrict__ Wt, const float* __restrict__ X,
    const float* __restrict__ bias, const float* __restrict__ mask,
    float* __restrict__ out, int M, int N, int K, float scale)
{
    __shared__ float As[16][132];   // [k][m] transposed
    __shared__ float Bs[16][128];   // [k][n]
    int b = blockIdx.z;
    const float* Xb = X + (size_t)b*K*N;
    float* Ob = out + (size_t)b*M*N;
    int m0 = blockIdx.y*128, n0 = blockIdx.x*128;
    int tid = threadIdx.x;
    int tx = tid & 15, ty = tid >> 4;
    int am = tid >> 2, ak = (tid & 3) * 4;     // A loader: m=am(+64), k=ak..ak+3
    int bk = tid >> 5, bn = (tid & 31) * 4;    // B loader: k=bk(+8),  n=bn..bn+3

    float acc[8][8];
    #pragma unroll
    for (int r=0;r<8;r++)
        #pragma unroll
        for (int c=0;c<8;c++) acc[r][c]=0.f;

    float4 mk4 = make_float4(1.f,1.f,1.f,1.f);
    if (MASK_IN) mk4 = *(const float4*)&mask[(size_t)b*TT + n0 + bn];

    for (int k0 = 0; k0 < K; k0 += 16) {
        #pragma unroll
        for (int p=0;p<2;p++){
            float4 a4 = *(const float4*)&Wt[(size_t)(m0+am+p*64)*K + k0 + ak];
            As[ak+0][am+p*64]=a4.x; As[ak+1][am+p*64]=a4.y;
            As[ak+2][am+p*64]=a4.z; As[ak+3][am+p*64]=a4.w;
        }
        #pragma unroll
        for (int p=0;p<2;p++){
            float4 b4 = *(const float4*)&Xb[(size_t)(k0+bk+p*8)*N + n0 + bn];
            if (MASK_IN){ b4.x*=mk4.x; b4.y*=mk4.y; b4.z*=mk4.z; b4.w*=mk4.w; }
            *(float4*)&Bs[bk+p*8][bn] = b4;
        }
        __syncthreads();
        #pragma unroll
        for (int kk=0;kk<16;kk++){
            float a[8], bb[8];
            *(float4*)&a[0]  = *(const float4*)&As[kk][ty*8];
            *(float4*)&a[4]  = *(const float4*)&As[kk][ty*8+4];
            *(float4*)&bb[0] = *(const float4*)&Bs[kk][tx*8];
            *(float4*)&bb[4] = *(const float4*)&Bs[kk][tx*8+4];
            #pragma unroll
            for (int r=0;r<8;r++)
                #pragma unroll
                for (int c=0;c<8;c++)
                    acc[r][c] += a[r]*bb[c];
        }
        __syncthreads();
    }

    float mo[8];
    if (MASK_OUT){
        #pragma unroll
        for (int c=0;c<8;c++) mo[c] = mask[(size_t)b*TT + n0 + tx*8 + c];
    }
    #pragma unroll
    for (int r=0;r<8;r++){
        int m = m0 + ty*8 + r;
        float bv = bias[m];
        float vrow[8];
        #pragma unroll
        for (int c=0;c<8;c++){
            float vv = acc[r][c] + bv;
            if (DO_SCALE) vv *= scale;
            if (RELU)     vv = fmaxf(vv, 0.f);
            if (MASK_OUT) vv *= mo[c];
            vrow[c]=vv;
        }
        *(float4*)&Ob[(size_t)m*N + n0 + tx*8]     = make_float4(vrow[0],vrow[1],vrow[2],vrow[3]);
        *(float4*)&Ob[(size_t)m*N + n0 + tx*8 + 4] = make_float4(vrow[4],vrow[5],vrow[6],vrow[7]);
    }
}

// ---------------- flash attention with relative positions ----------------
// grid (T/64, H, B), 256 threads, dynamic smem. q,k,v,o in (B,C,T) layout (c = h*64+d).
__global__ void __launch_bounds__(256) attn_kernel(
    const float* __restrict__ q, const float* __restrict__ k, const float* __restrict__ v,
    const float* __restrict__ relk, const float* __restrict__ relv,
    const float* __restrict__ mask, float* __restrict__ o)
{
    extern __shared__ float sm[];
    float* sQt   = sm;                     // [64 d][ASTRIDE] (d,i)
    float* sKt   = sQt + 64*ASTRIDE;       // [64 d][ASTRIDE] (d,j); reused as sP [i][j], then [d][i] out stage
    float* sV    = sKt + 64*ASTRIDE;       // [64 j][ASTRIDE] (j,d)
    float* sRK   = sV  + 64*ASTRIDE;       // [9][64]
    float* sRV   = sRK + RNUM*64;          // [9][64]
    float* sQRK  = sRV + RNUM*64;          // [64][9]
    float* sMask = sQRK + 64*RNUM;         // [64]

    int tid = threadIdx.x;
    int tx = tid & 15, ty = tid >> 4;
    int i0 = blockIdx.x * 64;
    int h  = blockIdx.y;
    int b  = blockIdx.z;
    const size_t hb = ((size_t)b*CC + h*HDD) * TT;

    // load Q tile transposed (d,i)
    #pragma unroll
    for (int p = 0; p < 4; p++) {
        int d  = (tid >> 4) + p*16;
        int iv = (tid & 15) * 4;
        *(float4*)&sQt[d*ASTRIDE + iv] = *(const float4*)&q[hb + (size_t)d*TT + i0 + iv];
    }
    for (int idx = tid; idx < RNUM*64; idx += 256) { sRK[idx] = relk[idx]; sRV[idx] = relv[idx]; }
    __syncthreads();

    // precompute q . rel_k : [64 i][9]
    for (int idx = tid; idx < 64*RNUM; idx += 256) {
        int ii = idx / RNUM, r = idx % RNUM;
        float s = 0.f;
        #pragma unroll 8
        for (int d = 0; d < 64; d++) s += sQt[d*ASTRIDE + ii] * sRK[r*64 + d];
        sQRK[idx] = s;
    }
    __syncthreads();

    float m_run[4], l_run[4], acc[4][4];
    #pragma unroll
    for (int r=0;r<4;r++){
        m_run[r]=-1e30f; l_run[r]=0.f;
        #pragma unroll
        for(int c=0;c<4;c++) acc[r][c]=0.f;
    }
    int iib = ty*4, jjb = tx*4;

    for (int jt = 0; jt < TT/64; jt++) {
        int j0 = jt*64;
        #pragma unroll
        for (int p=0;p<4;p++){
            int d  = (tid>>4) + p*16;
            int jv = (tid&15)*4;
            *(float4*)&sKt[d*ASTRIDE + jv] = *(const float4*)&k[hb + (size_t)d*TT + j0 + jv];
            float4 vv = *(const float4*)&v[hb + (size_t)d*TT + j0 + jv];
            sV[(jv+0)*ASTRIDE + d] = vv.x;
            sV[(jv+1)*ASTRIDE + d] = vv.y;
            sV[(jv+2)*ASTRIDE + d] = vv.z;
            sV[(jv+3)*ASTRIDE + d] = vv.w;
        }
        if (tid < 64) sMask[tid] = mask[(size_t)b*TT + j0 + tid];
        __syncthreads();

        // S = Q K^T
        float S[4][4];
        #pragma unroll
        for (int r=0;r<4;r++)
            #pragma unroll
            for(int c=0;c<4;c++) S[r][c]=0.f;
        #pragma unroll 8
        for (int d=0; d<64; d++){
            float4 a  = *(const float4*)&sQt[d*ASTRIDE + iib];
            float4 bb = *(const float4*)&sKt[d*ASTRIDE + jjb];
            float av[4] = {a.x,a.y,a.z,a.w};
            float bv[4] = {bb.x,bb.y,bb.z,bb.w};
            #pragma unroll
            for (int r=0;r<4;r++)
                #pragma unroll
                for (int c=0;c<4;c++) S[r][c] += av[r]*bv[c];
        }
        // rel-k band + mask
        #pragma unroll
        for (int r=0;r<4;r++){
            int ig = i0 + iib + r;
            #pragma unroll
            for (int c=0;c<4;c++){
                int jg = j0 + jjb + c;
                int delta = jg - ig;
                if (delta >= -WW && delta <= WW) S[r][c] += sQRK[(iib+r)*RNUM + delta + WW];
                if (sMask[jjb+c] == 0.f) S[r][c] = -1e30f;
            }
        }
        __syncthreads();   // done reading sKt

        // online softmax (row reduction over 16-lane tx groups)
        #pragma unroll
        for (int r=0;r<4;r++){
            float tm = fmaxf(fmaxf(S[r][0],S[r][1]), fmaxf(S[r][2],S[r][3]));
            #pragma unroll
            for (int off=8; off>=1; off>>=1) tm = fmaxf(tm, __shfl_xor_sync(0xffffffffu, tm, off));
            float mn = fmaxf(m_run[r], tm);
            float co = __expf(m_run[r] - mn);
            float rs = 0.f;
            #pragma unroll
            for (int c=0;c<4;c++){ float p = __expf(S[r][c]-mn); S[r][c]=p; rs += p; }
            #pragma unroll
            for (int off=8; off>=1; off>>=1) rs += __shfl_xor_sync(0xffffffffu, rs, off);
            l_run[r] = l_run[r]*co + rs;
            m_run[r] = mn;
            #pragma unroll
            for (int c=0;c<4;c++) acc[r][c] *= co;
            *(float4*)&sKt[(iib+r)*ASTRIDE + jjb] = make_float4(S[r][0],S[r][1],S[r][2],S[r][3]);
        }
        __syncthreads();

        // O += P V  (acc[r][c] = O[iib+r][d = tx*4+c])
        #pragma unroll 4
        for (int jj=0; jj<64; jj++){
            float4 vv = *(const float4*)&sV[jj*ASTRIDE + jjb];
            float pv[4];
            #pragma unroll
            for (int r=0;r<4;r++) pv[r] = sKt[(iib+r)*ASTRIDE + jj];
            float vvv[4]={vv.x,vv.y,vv.z,vv.w};
            #pragma unroll
            for (int r=0;r<4;r++)
                #pragma unroll
                for(int c=0;c<4;c++) acc[r][c] += pv[r]*vvv[c];
        }
        // O += P_band * rel_v
        #pragma unroll
        for (int r=0;r<4;r++){
            int ii = iib + r;
            int ig = i0 + ii;
            #pragma unroll
            for (int dlt=-WW; dlt<=WW; dlt++){
                int jj = ig + dlt - j0;
                if (jj >= 0 && jj < 64){
                    float pval = sKt[ii*ASTRIDE + jj];
                    const float* rvp = &sRV[(dlt+WW)*64 + jjb];
                    #pragma unroll
                    for (int c=0;c<4;c++) acc[r][c] += pval * rvp[c];
                }
            }
        }
        __syncthreads();
    }

    // normalize & write out via smem stage [d][i] for coalesced t-writes
    #pragma unroll
    for (int r=0;r<4;r++){
        float inv = 1.f / l_run[r];
        #pragma unroll
        for (int c=0;c<4;c++) sKt[(jjb+c)*ASTRIDE + iib + r] = acc[r][c]*inv;
    }
    __syncthreads();
    #pragma unroll
    for (int p=0;p<4;p++){
        int d  = (tid>>4) + p*16;
        int iv = (tid&15)*4;
        *(float4*)&o[hb + (size_t)d*TT + i0 + iv] = *(const float4*)&sKt[d*ASTRIDE + iv];
    }
}

// ---------------- fused residual + LayerNorm over C (+optional mask) ----------------
// grid (T/32, B), 256 threads = 8 c-groups x 32 t. In-place safe (each element touched by one thread).
__global__ void __launch_bounds__(256) add_ln_kernel(
    const float* __restrict__ res, const float* __restrict__ y,
    const float* __restrict__ g, const float* __restrict__ beta,
    const float* __restrict__ mask, int use_mask, float* __restrict__ dst)
{
    __shared__ float sS[8][32], sS2[8][32];
    int b  = blockIdx.y;
    int tt = threadIdx.x & 31;
    int cg = threadIdx.x >> 5;
    int t  = blockIdx.x*32 + tt;
    size_t base = (size_t)b*CC*TT + t;
    float s=0.f, s2=0.f;
    for (int c=cg; c<CC; c+=8){
        float vv = res[base + (size_t)c*TT] + y[base + (size_t)c*TT];
        s += vv; s2 += vv*vv;
    }
    sS[cg][tt]=s; sS2[cg][tt]=s2;
    __syncthreads();
    if (cg==0){
        #pragma unroll
        for (int i=1;i<8;i++){ s += sS[i][tt]; s2 += sS2[i][tt]; }
        float mean = s * (1.f/CC);
        float var  = s2 * (1.f/CC) - mean*mean;
        sS[0][tt]  = mean;
        sS2[0][tt] = rsqrtf(var + 1e-6f);
    }
    __syncthreads();
    float mean = sS[0][tt], inv = sS2[0][tt];
    float mk = use_mask ? mask[(size_t)b*TT + t] : 1.f;
    for (int c=cg; c<CC; c+=8){
        float vv  = res[base + (size_t)c*TT] + y[base + (size_t)c*TT];
        float ovv = (vv-mean)*inv*g[c] + beta[c];
        dst[base + (size_t)c*TT] = ovv*mk;
    }
}

#define ATTN_SMEM_BYTES ((3*64*ASTRIDE + 2*RNUM*64 + 64*RNUM + 64) * (int)sizeof(float))

extern "C" void kernel_launch(void* const* d_in, const int* in_sizes, int n_in,
                              void* d_out, int out_size)
{
    const float* x    = (const float*)d_in[0];
    const float* mask = (const float*)d_in[1];
    const float* qw   = (const float*)d_in[2];
    const float* qb   = (const float*)d_in[3];
    const float* kw   = (const float*)d_in[4];
    const float* kb   = (const float*)d_in[5];
    const float* vw   = (const float*)d_in[6];
    const float* vb   = (const float*)d_in[7];
    const float* ow   = (const float*)d_in[8];
    const float* ob   = (const float*)d_in[9];
    const float* rk   = (const float*)d_in[10];
    const float* rv   = (const float*)d_in[11];
    const float* ln1g = (const float*)d_in[12];
    const float* ln1b = (const float*)d_in[13];
    const float* w1   = (const float*)d_in[14];
    const float* b1   = (const float*)d_in[15];
    const float* w2   = (const float*)d_in[16];
    const float* b2   = (const float*)d_in[17];
    const float* ln2g = (const float*)d_in[18];
    const float* ln2b = (const float*)d_in[19];

    float *gx,*gq,*gk,*gv,*go,*gt,*gh;
    cudaGetSymbolAddress((void**)&gx, g_x);
    cudaGetSymbolAddress((void**)&gq, g_q);
    cudaGetSymbolAddress((void**)&gk, g_k);
    cudaGetSymbolAddress((void**)&gv, g_v);
    cudaGetSymbolAddress((void**)&go, g_o);
    cudaGetSymbolAddress((void**)&gt, g_t);
    cudaGetSymbolAddress((void**)&gh, g_h);

    cudaFuncSetAttribute(attn_kernel, cudaFuncAttributeMaxDynamicSharedMemorySize, ATTN_SMEM_BYTES);

    cudaMemcpyAsync(gx, x, sizeof(float)*BB*CC*TT, cudaMemcpyDeviceToDevice, 0);

    const float inv_scale = 0.125f; // 1/sqrt(64)
    dim3 blk(256);
    for (int i=0;i<LL;i++){
        size_t wofs = (size_t)i*CC*CC;
        gemm_kernel<0,0,0,1><<<dim3(TT/128, CC/128, BB), blk>>>(qw+wofs, gx, qb+i*CC, mask, gq, CC, TT, CC, inv_scale);
        gemm_kernel<0,0,0,0><<<dim3(TT/128, CC/128, BB), blk>>>(kw+wofs, gx, kb+i*CC, mask, gk, CC, TT, CC, 1.f);
        gemm_kernel<0,0,0,0><<<dim3(TT/128, CC/128, BB), blk>>>(vw+wofs, gx, vb+i*CC, mask, gv, CC, TT, CC, 1.f);
        attn_kernel<<<dim3(TT/64, HH, BB), blk, ATTN_SMEM_BYTES>>>(gq, gk, gv,
            rk + (size_t)i*RNUM*HDD, rv + (size_t)i*RNUM*HDD, mask, go);
        gemm_kernel<0,0,0,0><<<dim3(TT/128, CC/128, BB), blk>>>(ow+wofs, go, ob+i*CC, mask, gt, CC, TT, CC, 1.f);
        add_ln_kernel<<<dim3(TT/32, BB), blk>>>(gx, gt, ln1g+i*CC, ln1b+i*CC, mask, 0, gx);
        gemm_kernel<1,1,1,0><<<dim3(TT/128, FF/128, BB), blk>>>(w1+(size_t)i*FF*CC, gx, b1+i*FF, mask, gh, FF, TT, CC, 1.f);
        gemm_kernel<0,0,1,0><<<dim3(TT/128, CC/128, BB), blk>>>(w2+(size_t)i*CC*FF, gh, b2+i*CC, mask, gt, CC, TT, FF, 1.f);
        float* dst = (i==LL-1) ? (float*)d_out : gx;
        add_ln_kernel<<<dim3(TT/32, BB), blk>>>(gx, gt, ln2g+i*CC, ln2b+i*CC, mask, 1, dst);
    }
}

// round 2
// speedup vs baseline: 1.5067x; 1.5067x over previous
#include <cuda_runtime.h>
#include <cuda_bf16.h>
#include <math.h>

#define BB 4
#define CC 512
#define TT 1024
#define HH 8
#define HDD 64
#define FF 2048
#define LL 4
#define WW 4
#define RNUM 9
#define ASTRIDE 68

// ---------------- scratch (no allocations allowed) ----------------
__device__ float g_x[BB*CC*TT];
__device__ float g_q[BB*CC*TT];
__device__ float g_k[BB*CC*TT];
__device__ float g_v[BB*CC*TT];
__device__ float g_o[BB*CC*TT];
__device__ float g_t[BB*CC*TT];
__device__ float g_h[BB*FF*TT];

// ---------------- mma helpers ----------------
__device__ __forceinline__ void mma16816(float* d, const unsigned* a, const unsigned* b){
    asm volatile("mma.sync.aligned.m16n8k16.row.col.f32.bf16.bf16.f32 "
        "{%0,%1,%2,%3}, {%4,%5,%6,%7}, {%8,%9}, {%0,%1,%2,%3};"
        : "+f"(d[0]),"+f"(d[1]),"+f"(d[2]),"+f"(d[3])
        : "r"(a[0]),"r"(a[1]),"r"(a[2]),"r"(a[3]), "r"(b[0]),"r"(b[1]));
}
__device__ __forceinline__ void ldsm4(unsigned* r, const void* p){
    unsigned addr = (unsigned)__cvta_generic_to_shared(p);
    asm volatile("ldmatrix.sync.aligned.m8n8.x4.shared.b16 {%0,%1,%2,%3}, [%4];"
        : "=r"(r[0]),"=r"(r[1]),"=r"(r[2]),"=r"(r[3]) : "r"(addr));
}
__device__ __forceinline__ void ldsm2t(unsigned* r, const void* p){
    unsigned addr = (unsigned)__cvta_generic_to_shared(p);
    asm volatile("ldmatrix.sync.aligned.m8n8.x2.trans.shared.b16 {%0,%1}, [%2];"
        : "=r"(r[0]),"=r"(r[1]) : "r"(addr));
}
__device__ __forceinline__ void split_bf16(float v, __nv_bfloat16& h, __nv_bfloat16& l){
    h = __float2bfloat16(v);
    l = __float2bfloat16(v - __bfloat162float(h));
}

// ---------------- split-bf16 tensor-core GEMM ----------------
// out[b][m][n] = sum_k W[m][k] X[b][k][n] (+bias, epilogue)
// tile 128x128x32, 256 threads (8 warps, 64x32 warp tiles), 3-pass hi/lo mma.
template<int RELU, int MASK_IN, int MASK_OUT, int DO_SCALE>
__global__ void __launch_bounds__(256,2) gemm_mma_kernel(
    const float* __restrict__ Wt, const float* __restrict__ X,
    const float* __restrict__ bias, const float* __restrict__ mask,
    float* __restrict__ out, int M, int N, int K, float scale)
{
    __shared__ __nv_bfloat16 As_h[128][40];
    __shared__ __nv_bfloat16 As_l[128][40];
    __shared__ __nv_bfloat16 Bs_h[32][136];
    __shared__ __nv_bfloat16 Bs_l[32][136];

    int b = blockIdx.z;
    const float* Xb = X + (size_t)b*K*N;
    float* Ob = out + (size_t)b*M*N;
    int m0 = blockIdx.y*128, n0 = blockIdx.x*128;
    int tid = threadIdx.x;
    int l = tid & 31, w = tid >> 5;
    int wm0 = (w >> 2) * 64;     // warp m offset in tile
    int wn0 = (w & 3) * 32;      // warp n offset in tile

    float acc[4][4][4];
    #pragma unroll
    for (int mi=0;mi<4;mi++)
        #pragma unroll
        for (int ni=0;ni<4;ni++)
            #pragma unroll
            for (int e=0;e<4;e++) acc[mi][ni][e]=0.f;

    for (int k0 = 0; k0 < K; k0 += 32) {
        // load A 128x32 fp32 -> split bf16
        #pragma unroll
        for (int p=0;p<4;p++){
            int lin = tid + p*256;
            int am = lin >> 3;
            int ak = (lin & 7) * 4;
            float4 a4 = *(const float4*)&Wt[(size_t)(m0+am)*K + k0 + ak];
            __nv_bfloat16 h0,l0,h1,l1,h2,l2,h3,l3;
            split_bf16(a4.x,h0,l0); split_bf16(a4.y,h1,l1);
            split_bf16(a4.z,h2,l2); split_bf16(a4.w,h3,l3);
            *(__nv_bfloat162*)&As_h[am][ak]   = __nv_bfloat162(h0,h1);
            *(__nv_bfloat162*)&As_h[am][ak+2] = __nv_bfloat162(h2,h3);
            *(__nv_bfloat162*)&As_l[am][ak]   = __nv_bfloat162(l0,l1);
            *(__nv_bfloat162*)&As_l[am][ak+2] = __nv_bfloat162(l2,l3);
        }
        // load B 32x128 fp32 -> split bf16 (optional input mask over n)
        #pragma unroll
        for (int p=0;p<4;p++){
            int lin = tid + p*256;
            int bk = lin >> 5;
            int bn = (lin & 31) * 4;
            float4 b4 = *(const float4*)&Xb[(size_t)(k0+bk)*N + n0 + bn];
            if (MASK_IN){
                float4 mk = *(const float4*)&mask[(size_t)b*TT + n0 + bn];
                b4.x*=mk.x; b4.y*=mk.y; b4.z*=mk.z; b4.w*=mk.w;
            }
            __nv_bfloat16 h0,l0,h1,l1,h2,l2,h3,l3;
            split_bf16(b4.x,h0,l0); split_bf16(b4.y,h1,l1);
            split_bf16(b4.z,h2,l2); split_bf16(b4.w,h3,l3);
            *(__nv_bfloat162*)&Bs_h[bk][bn]   = __nv_bfloat162(h0,h1);
            *(__nv_bfloat162*)&Bs_h[bk][bn+2] = __nv_bfloat162(h2,h3);
            *(__nv_bfloat162*)&Bs_l[bk][bn]   = __nv_bfloat162(l0,l1);
            *(__nv_bfloat162*)&Bs_l[bk][bn+2] = __nv_bfloat162(l2,l3);
        }
        __syncthreads();

        #pragma unroll
        for (int ks=0; ks<32; ks+=16){
            unsigned Bh[4][2], Bl[4][2];
            #pragma unroll
            for (int ni=0;ni<4;ni++){
                ldsm2t(Bh[ni], &Bs_h[ks + (l & 15)][wn0 + ni*8]);
                ldsm2t(Bl[ni], &Bs_l[ks + (l & 15)][wn0 + ni*8]);
            }
            #pragma unroll
            for (int mi=0;mi<4;mi++){
                unsigned Ah[4], Al[4];
                ldsm4(Ah, &As_h[wm0 + mi*16 + (l & 15)][ks + (l >> 4)*8]);
                ldsm4(Al, &As_l[wm0 + mi*16 + (l & 15)][ks + (l >> 4)*8]);
                #pragma unroll
                for (int ni=0;ni<4;ni++){
                    mma16816(acc[mi][ni], Ah, Bh[ni]);
                    mma16816(acc[mi][ni], Al, Bh[ni]);
                    mma16816(acc[mi][ni], Ah, Bl[ni]);
                }
            }
        }
        __syncthreads();
    }

    // epilogue
    #pragma unroll
    for (int mi=0;mi<4;mi++){
        int r = m0 + wm0 + mi*16 + (l >> 2);
        float bv0 = bias[r], bv1 = bias[r+8];
        #pragma unroll
        for (int ni=0;ni<4;ni++){
            int cn = n0 + wn0 + ni*8 + (l & 3)*2;
            float m00=1.f, m01=1.f;
            if (MASK_OUT){
                m00 = mask[(size_t)b*TT + cn];
                m01 = mask[(size_t)b*TT + cn + 1];
            }
            float c0 = acc[mi][ni][0] + bv0;
            float c1 = acc[mi][ni][1] + bv0;
            float c2 = acc[mi][ni][2] + bv1;
            float c3 = acc[mi][ni][3] + bv1;
            if (DO_SCALE){ c0*=scale; c1*=scale; c2*=scale; c3*=scale; }
            if (RELU){ c0=fmaxf(c0,0.f); c1=fmaxf(c1,0.f); c2=fmaxf(c2,0.f); c3=fmaxf(c3,0.f); }
            if (MASK_OUT){ c0*=m00; c1*=m01; c2*=m00; c3*=m01; }
            *(float2*)&Ob[(size_t)r*N + cn]     = make_float2(c0,c1);
            *(float2*)&Ob[(size_t)(r+8)*N + cn] = make_float2(c2,c3);
        }
    }
}

// ---------------- flash attention with relative positions ----------------
__global__ void __launch_bounds__(256) attn_kernel(
    const float* __restrict__ q, const float* __restrict__ k, const float* __restrict__ v,
    const float* __restrict__ relk, const float* __restrict__ relv,
    const float* __restrict__ mask, float* __restrict__ o)
{
    extern __shared__ float sm[];
    float* sQt   = sm;                     // [64 d][ASTRIDE] (d,i)
    float* sKt   = sQt + 64*ASTRIDE;       // [64 d][ASTRIDE] (d,j); reused as sP, then out stage
    float* sV    = sKt + 64*ASTRIDE;       // [64 j][ASTRIDE] (j,d)
    float* sRK   = sV  + 64*ASTRIDE;       // [9][64]
    float* sRV   = sRK + RNUM*64;          // [9][64]
    float* sQRK  = sRV + RNUM*64;          // [64][9]
    float* sMask = sQRK + 64*RNUM;         // [64]

    int tid = threadIdx.x;
    int tx = tid & 15, ty = tid >> 4;
    int i0 = blockIdx.x * 64;
    int h  = blockIdx.y;
    int b  = blockIdx.z;
    const size_t hb = ((size_t)b*CC + h*HDD) * TT;

    #pragma unroll
    for (int p = 0; p < 4; p++) {
        int d  = (tid >> 4) + p*16;
        int iv = (tid & 15) * 4;
        *(float4*)&sQt[d*ASTRIDE + iv] = *(const float4*)&q[hb + (size_t)d*TT + i0 + iv];
    }
    for (int idx = tid; idx < RNUM*64; idx += 256) { sRK[idx] = relk[idx]; sRV[idx] = relv[idx]; }
    __syncthreads();

    for (int idx = tid; idx < 64*RNUM; idx += 256) {
        int ii = idx / RNUM, r = idx % RNUM;
        float s = 0.f;
        #pragma unroll 8
        for (int d = 0; d < 64; d++) s += sQt[d*ASTRIDE + ii] * sRK[r*64 + d];
        sQRK[idx] = s;
    }
    __syncthreads();

    float m_run[4], l_run[4], acc[4][4];
    #pragma unroll
    for (int r=0;r<4;r++){
        m_run[r]=-1e30f; l_run[r]=0.f;
        #pragma unroll
        for(int c=0;c<4;c++) acc[r][c]=0.f;
    }
    int iib = ty*4, jjb = tx*4;

    for (int jt = 0; jt < TT/64; jt++) {
        int j0 = jt*64;
        #pragma unroll
        for (int p=0;p<4;p++){
            int d  = (tid>>4) + p*16;
            int jv = (tid&15)*4;
            *(float4*)&sKt[d*ASTRIDE + jv] = *(const float4*)&k[hb + (size_t)d*TT + j0 + jv];
            float4 vv = *(const float4*)&v[hb + (size_t)d*TT + j0 + jv];
            sV[(jv+0)*ASTRIDE + d] = vv.x;
            sV[(jv+1)*ASTRIDE + d] = vv.y;
            sV[(jv+2)*ASTRIDE + d] = vv.z;
            sV[(jv+3)*ASTRIDE + d] = vv.w;
        }
        if (tid < 64) sMask[tid] = mask[(size_t)b*TT + j0 + tid];
        __syncthreads();

        float S[4][4];
        #pragma unroll
        for (int r=0;r<4;r++)
            #pragma unroll
            for(int c=0;c<4;c++) S[r][c]=0.f;
        #pragma unroll 8
        for (int d=0; d<64; d++){
            float4 a  = *(const float4*)&sQt[d*ASTRIDE + iib];
            float4 bb = *(const float4*)&sKt[d*ASTRIDE + jjb];
            float av[4] = {a.x,a.y,a.z,a.w};
            float bv[4] = {bb.x,bb.y,bb.z,bb.w};
            #pragma unroll
            for (int r=0;r<4;r++)
                #pragma unroll
                for (int c=0;c<4;c++) S[r][c] += av[r]*bv[c];
        }
        #pragma unroll
        for (int r=0;r<4;r++){
            int ig = i0 + iib + r;
            #pragma unroll
            for (int c=0;c<4;c++){
                int jg = j0 + jjb + c;
                int delta = jg - ig;
                if (delta >= -WW && delta <= WW) S[r][c] += sQRK[(iib+r)*RNUM + delta + WW];
                if (sMask[jjb+c] == 0.f) S[r][c] = -1e30f;
            }
        }
        __syncthreads();

        #pragma unroll
        for (int r=0;r<4;r++){
            float tm = fmaxf(fmaxf(S[r][0],S[r][1]), fmaxf(S[r][2],S[r][3]));
            #pragma unroll
            for (int off=8; off>=1; off>>=1) tm = fmaxf(tm, __shfl_xor_sync(0xffffffffu, tm, off));
            float mn = fmaxf(m_run[r], tm);
            float co = __expf(m_run[r] - mn);
            float rs = 0.f;
            #pragma unroll
            for (int c=0;c<4;c++){ float p = __expf(S[r][c]-mn); S[r][c]=p; rs += p; }
            #pragma unroll
            for (int off=8; off>=1; off>>=1) rs += __shfl_xor_sync(0xffffffffu, rs, off);
            l_run[r] = l_run[r]*co + rs;
            m_run[r] = mn;
            #pragma unroll
            for (int c=0;c<4;c++) acc[r][c] *= co;
            *(float4*)&sKt[(iib+r)*ASTRIDE + jjb] = make_float4(S[r][0],S[r][1],S[r][2],S[r][3]);
        }
        __syncthreads();

        #pragma unroll 4
        for (int jj=0; jj<64; jj++){
            float4 vv = *(const float4*)&sV[jj*ASTRIDE + jjb];
            float pv[4];
            #pragma unroll
            for (int r=0;r<4;r++) pv[r] = sKt[(iib+r)*ASTRIDE + jj];
            float vvv[4]={vv.x,vv.y,vv.z,vv.w};
            #pragma unroll
            for (int r=0;r<4;r++)
                #pragma unroll
                for(int c=0;c<4;c++) acc[r][c] += pv[r]*vvv[c];
        }
        #pragma unroll
        for (int r=0;r<4;r++){
            int ii = iib + r;
            int ig = i0 + ii;
            #pragma unroll
            for (int dlt=-WW; dlt<=WW; dlt++){
                int jj = ig + dlt - j0;
                if (jj >= 0 && jj < 64){
                    float pval = sKt[ii*ASTRIDE + jj];
                    const float* rvp = &sRV[(dlt+WW)*64 + jjb];
                    #pragma unroll
                    for (int c=0;c<4;c++) acc[r][c] += pval * rvp[c];
                }
            }
        }
        __syncthreads();
    }

    #pragma unroll
    for (int r=0;r<4;r++){
        float inv = 1.f / l_run[r];
        #pragma unroll
        for (int c=0;c<4;c++) sKt[(jjb+c)*ASTRIDE + iib + r] = acc[r][c]*inv;
    }
    __syncthreads();
    #pragma unroll
    for (int p=0;p<4;p++){
        int d  = (tid>>4) + p*16;
        int iv = (tid&15)*4;
        *(float4*)&o[hb + (size_t)d*TT + i0 + iv] = *(const float4*)&sKt[d*ASTRIDE + iv];
    }
}

// ---------------- fused residual + LayerNorm over C (+optional mask) ----------------
__global__ void __launch_bounds__(256) add_ln_kernel(
    const float* __restrict__ res, const float* __restrict__ y,
    const float* __restrict__ g, const float* __restrict__ beta,
    const float* __restrict__ mask, int use_mask, float* __restrict__ dst)
{
    __shared__ float sS[8][32], sS2[8][32];
    int b  = blockIdx.y;
    int tt = threadIdx.x & 31;
    int cg = threadIdx.x >> 5;
    int t  = blockIdx.x*32 + tt;
    size_t base = (size_t)b*CC*TT + t;
    float s=0.f, s2=0.f;
    for (int c=cg; c<CC; c+=8){
        float vv = res[base + (size_t)c*TT] + y[base + (size_t)c*TT];
        s += vv; s2 += vv*vv;
    }
    sS[cg][tt]=s; sS2[cg][tt]=s2;
    __syncthreads();
    if (cg==0){
        #pragma unroll
        for (int i=1;i<8;i++){ s += sS[i][tt]; s2 += sS2[i][tt]; }
        float mean = s * (1.f/CC);
        float var  = s2 * (1.f/CC) - mean*mean;
        sS[0][tt]  = mean;
        sS2[0][tt] = rsqrtf(var + 1e-6f);
    }
    __syncthreads();
    float mean = sS[0][tt], inv = sS2[0][tt];
    float mk = use_mask ? mask[(size_t)b*TT + t] : 1.f;
    for (int c=cg; c<CC; c+=8){
        float vv  = res[base + (size_t)c*TT] + y[base + (size_t)c*TT];
        float ovv = (vv-mean)*inv*g[c] + beta[c];
        dst[base + (size_t)c*TT] = ovv*mk;
    }
}

#define ATTN_SMEM_BYTES ((3*64*ASTRIDE + 2*RNUM*64 + 64*RNUM + 64) * (int)sizeof(float))

extern "C" void kernel_launch(void* const* d_in, const int* in_sizes, int n_in,
                              void* d_out, int out_size)
{
    const float* x    = (const float*)d_in[0];
    const float* mask = (const float*)d_in[1];
    const float* qw   = (const float*)d_in[2];
    const float* qb   = (const float*)d_in[3];
    const float* kw   = (const float*)d_in[4];
    const float* kb   = (const float*)d_in[5];
    const float* vw   = (const float*)d_in[6];
    const float* vb   = (const float*)d_in[7];
    const float* ow   = (const float*)d_in[8];
    const float* ob   = (const float*)d_in[9];
    const float* rk   = (const float*)d_in[10];
    const float* rv   = (const float*)d_in[11];
    const float* ln1g = (const float*)d_in[12];
    const float* ln1b = (const float*)d_in[13];
    const float* w1   = (const float*)d_in[14];
    const float* b1   = (const float*)d_in[15];
    const float* w2   = (const float*)d_in[16];
    const float* b2   = (const float*)d_in[17];
    const float* ln2g = (const float*)d_in[18];
    const float* ln2b = (const float*)d_in[19];

    float *gx,*gq,*gk,*gv,*go,*gt,*gh;
    cudaGetSymbolAddress((void**)&gx, g_x);
    cudaGetSymbolAddress((void**)&gq, g_q);
    cudaGetSymbolAddress((void**)&gk, g_k);
    cudaGetSymbolAddress((void**)&gv, g_v);
    cudaGetSymbolAddress((void**)&go, g_o);
    cudaGetSymbolAddress((void**)&gt, g_t);
    cudaGetSymbolAddress((void**)&gh, g_h);

    cudaFuncSetAttribute(attn_kernel, cudaFuncAttributeMaxDynamicSharedMemorySize, ATTN_SMEM_BYTES);

    cudaMemcpyAsync(gx, x, sizeof(float)*BB*CC*TT, cudaMemcpyDeviceToDevice, 0);

    const float inv_scale = 0.125f; // 1/sqrt(64)
    dim3 blk(256);
    for (int i=0;i<LL;i++){
        size_t wofs = (size_t)i*CC*CC;
        gemm_mma_kernel<0,0,0,1><<<dim3(TT/128, CC/128, BB), blk>>>(qw+wofs, gx, qb+i*CC, mask, gq, CC, TT, CC, inv_scale);
        gemm_mma_kernel<0,0,0,0><<<dim3(TT/128, CC/128, BB), blk>>>(kw+wofs, gx, kb+i*CC, mask, gk, CC, TT, CC, 1.f);
        gemm_mma_kernel<0,0,0,0><<<dim3(TT/128, CC/128, BB), blk>>>(vw+wofs, gx, vb+i*CC, mask, gv, CC, TT, CC, 1.f);
        attn_kernel<<<dim3(TT/64, HH, BB), blk, ATTN_SMEM_BYTES>>>(gq, gk, gv,
            rk + (size_t)i*RNUM*HDD, rv + (size_t)i*RNUM*HDD, mask, go);
        gemm_mma_kernel<0,0,0,0><<<dim3(TT/128, CC/128, BB), blk>>>(ow+wofs, go, ob+i*CC, mask, gt, CC, TT, CC, 1.f);
        add_ln_kernel<<<dim3(TT/32, BB), blk>>>(gx, gt, ln1g+i*CC, ln1b+i*CC, mask, 0, gx);
        gemm_mma_kernel<1,1,1,0><<<dim3(TT/128, FF/128, BB), blk>>>(w1+(size_t)i*FF*CC, gx, b1+i*FF, mask, gh, FF, TT, CC, 1.f);
        gemm_mma_kernel<0,0,1,0><<<dim3(TT/128, CC/128, BB), blk>>>(w2+(size_t)i*CC*FF, gh, b2+i*CC, mask, gt, CC, TT, FF, 1.f);
        float* dst = (i==LL-1) ? (float*)d_out : gx;
        add_ln_kernel<<<dim3(TT/32, BB), blk>>>(gx, gt, ln2g+i*CC, ln2b+i*CC, mask, 1, dst);
    }
}

// round 3
// speedup vs baseline: 1.9816x; 1.3152x over previous
#include <cuda_runtime.h>
#include <cuda_bf16.h>
#include <math.h>

#define BB 4
#define CC 512
#define TT 1024
#define HH 8
#define HDD 64
#define FF 2048
#define LL 4
#define WW 4
#define RNUM 9
#define QS 72   // bf16 stride for attn smem tiles

// ---------------- scratch (no allocations allowed) ----------------
__device__ float g_x[BB*CC*TT];
__device__ float g_q[BB*CC*TT];
__device__ float g_k[BB*CC*TT];
__device__ float g_v[BB*CC*TT];
__device__ float g_o[BB*CC*TT];
__device__ float g_t[BB*CC*TT];
__device__ float g_h[BB*FF*TT];

// ---------------- mma helpers ----------------
__device__ __forceinline__ void mma16816(float* d, const unsigned* a, const unsigned* b){
    asm volatile("mma.sync.aligned.m16n8k16.row.col.f32.bf16.bf16.f32 "
        "{%0,%1,%2,%3}, {%4,%5,%6,%7}, {%8,%9}, {%0,%1,%2,%3};"
        : "+f"(d[0]),"+f"(d[1]),"+f"(d[2]),"+f"(d[3])
        : "r"(a[0]),"r"(a[1]),"r"(a[2]),"r"(a[3]), "r"(b[0]),"r"(b[1]));
}
__device__ __forceinline__ void ldsm4(unsigned* r, const void* p){
    unsigned addr = (unsigned)__cvta_generic_to_shared(p);
    asm volatile("ldmatrix.sync.aligned.m8n8.x4.shared.b16 {%0,%1,%2,%3}, [%4];"
        : "=r"(r[0]),"=r"(r[1]),"=r"(r[2]),"=r"(r[3]) : "r"(addr));
}
__device__ __forceinline__ void ldsm4t(unsigned* r, const void* p){
    unsigned addr = (unsigned)__cvta_generic_to_shared(p);
    asm volatile("ldmatrix.sync.aligned.m8n8.x4.trans.shared.b16 {%0,%1,%2,%3}, [%4];"
        : "=r"(r[0]),"=r"(r[1]),"=r"(r[2]),"=r"(r[3]) : "r"(addr));
}
__device__ __forceinline__ void ldsm2t(unsigned* r, const void* p){
    unsigned addr = (unsigned)__cvta_generic_to_shared(p);
    asm volatile("ldmatrix.sync.aligned.m8n8.x2.trans.shared.b16 {%0,%1}, [%2];"
        : "=r"(r[0]),"=r"(r[1]) : "r"(addr));
}
__device__ __forceinline__ void split_bf16(float v, __nv_bfloat16& h, __nv_bfloat16& l){
    h = __float2bfloat16(v);
    l = __float2bfloat16(v - __bfloat162float(h));
}
__device__ __forceinline__ void split_pack2(float x, float y, unsigned& hp, unsigned& lp){
    __nv_bfloat16 hx, lx, hy, ly;
    split_bf16(x, hx, lx); split_bf16(y, hy, ly);
    __nv_bfloat162 th(hx, hy), tl(lx, ly);
    hp = *(unsigned*)&th; lp = *(unsigned*)&tl;
}

// ---------------- split-bf16 tensor-core GEMM ----------------
template<int RELU, int MASK_IN, int MASK_OUT, int DO_SCALE>
__global__ void __launch_bounds__(256,2) gemm_mma_kernel(
    const float* __restrict__ Wt, const float* __restrict__ X,
    const float* __restrict__ bias, const float* __restrict__ mask,
    float* __restrict__ out, int M, int N, int K, float scale)
{
    __shared__ __nv_bfloat16 As_h[128][40];
    __shared__ __nv_bfloat16 As_l[128][40];
    __shared__ __nv_bfloat16 Bs_h[32][136];
    __shared__ __nv_bfloat16 Bs_l[32][136];

    int b = blockIdx.z;
    const float* Xb = X + (size_t)b*K*N;
    float* Ob = out + (size_t)b*M*N;
    int m0 = blockIdx.y*128, n0 = blockIdx.x*128;
    int tid = threadIdx.x;
    int l = tid & 31, w = tid >> 5;
    int wm0 = (w >> 2) * 64;
    int wn0 = (w & 3) * 32;

    float acc[4][4][4];
    #pragma unroll
    for (int mi=0;mi<4;mi++)
        #pragma unroll
        for (int ni=0;ni<4;ni++)
            #pragma unroll
            for (int e=0;e<4;e++) acc[mi][ni][e]=0.f;

    for (int k0 = 0; k0 < K; k0 += 32) {
        #pragma unroll
        for (int p=0;p<4;p++){
            int lin = tid + p*256;
            int am = lin >> 3;
            int ak = (lin & 7) * 4;
            float4 a4 = *(const float4*)&Wt[(size_t)(m0+am)*K + k0 + ak];
            __nv_bfloat16 h0,l0,h1,l1,h2,l2,h3,l3;
            split_bf16(a4.x,h0,l0); split_bf16(a4.y,h1,l1);
            split_bf16(a4.z,h2,l2); split_bf16(a4.w,h3,l3);
            *(__nv_bfloat162*)&As_h[am][ak]   = __nv_bfloat162(h0,h1);
            *(__nv_bfloat162*)&As_h[am][ak+2] = __nv_bfloat162(h2,h3);
            *(__nv_bfloat162*)&As_l[am][ak]   = __nv_bfloat162(l0,l1);
            *(__nv_bfloat162*)&As_l[am][ak+2] = __nv_bfloat162(l2,l3);
        }
        #pragma unroll
        for (int p=0;p<4;p++){
            int lin = tid + p*256;
            int bk = lin >> 5;
            int bn = (lin & 31) * 4;
            float4 b4 = *(const float4*)&Xb[(size_t)(k0+bk)*N + n0 + bn];
            if (MASK_IN){
                float4 mk = *(const float4*)&mask[(size_t)b*TT + n0 + bn];
                b4.x*=mk.x; b4.y*=mk.y; b4.z*=mk.z; b4.w*=mk.w;
            }
            __nv_bfloat16 h0,l0,h1,l1,h2,l2,h3,l3;
            split_bf16(b4.x,h0,l0); split_bf16(b4.y,h1,l1);
            split_bf16(b4.z,h2,l2); split_bf16(b4.w,h3,l3);
            *(__nv_bfloat162*)&Bs_h[bk][bn]   = __nv_bfloat162(h0,h1);
            *(__nv_bfloat162*)&Bs_h[bk][bn+2] = __nv_bfloat162(h2,h3);
            *(__nv_bfloat162*)&Bs_l[bk][bn]   = __nv_bfloat162(l0,l1);
            *(__nv_bfloat162*)&Bs_l[bk][bn+2] = __nv_bfloat162(l2,l3);
        }
        __syncthreads();

        #pragma unroll
        for (int ks=0; ks<32; ks+=16){
            unsigned Bh[4][2], Bl[4][2];
            #pragma unroll
            for (int ni=0;ni<4;ni++){
                ldsm2t(Bh[ni], &Bs_h[ks + (l & 15)][wn0 + ni*8]);
                ldsm2t(Bl[ni], &Bs_l[ks + (l & 15)][wn0 + ni*8]);
            }
            #pragma unroll
            for (int mi=0;mi<4;mi++){
                unsigned Ah[4], Al[4];
                ldsm4(Ah, &As_h[wm0 + mi*16 + (l & 15)][ks + (l >> 4)*8]);
                ldsm4(Al, &As_l[wm0 + mi*16 + (l & 15)][ks + (l >> 4)*8]);
                #pragma unroll
                for (int ni=0;ni<4;ni++){
                    mma16816(acc[mi][ni], Ah, Bh[ni]);
                    mma16816(acc[mi][ni], Al, Bh[ni]);
                    mma16816(acc[mi][ni], Ah, Bl[ni]);
                }
            }
        }
        __syncthreads();
    }

    #pragma unroll
    for (int mi=0;mi<4;mi++){
        int r = m0 + wm0 + mi*16 + (l >> 2);
        float bv0 = bias[r], bv1 = bias[r+8];
        #pragma unroll
        for (int ni=0;ni<4;ni++){
            int cn = n0 + wn0 + ni*8 + (l & 3)*2;
            float m00=1.f, m01=1.f;
            if (MASK_OUT){
                m00 = mask[(size_t)b*TT + cn];
                m01 = mask[(size_t)b*TT + cn + 1];
            }
            float c0 = acc[mi][ni][0] + bv0;
            float c1 = acc[mi][ni][1] + bv0;
            float c2 = acc[mi][ni][2] + bv1;
            float c3 = acc[mi][ni][3] + bv1;
            if (DO_SCALE){ c0*=scale; c1*=scale; c2*=scale; c3*=scale; }
            if (RELU){ c0=fmaxf(c0,0.f); c1=fmaxf(c1,0.f); c2=fmaxf(c2,0.f); c3=fmaxf(c3,0.f); }
            if (MASK_OUT){ c0*=m00; c1*=m01; c2*=m00; c3*=m01; }
            *(float2*)&Ob[(size_t)r*N + cn]     = make_float2(c0,c1);
            *(float2*)&Ob[(size_t)(r+8)*N + cn] = make_float2(c2,c3);
        }
    }
}

// ---------------- tensor-core flash attention with relative positions ----------------
// grid (T/64, H, B), 128 threads (4 warps, 16 i-rows each). split-bf16 3-pass mma.
__global__ void __launch_bounds__(128) attn_mma_kernel(
    const float* __restrict__ q, const float* __restrict__ k, const float* __restrict__ v,
    const float* __restrict__ relk, const float* __restrict__ relv,
    const float* __restrict__ mask, float* __restrict__ o)
{
    extern __shared__ char smraw[];
    __nv_bfloat16* Qh = (__nv_bfloat16*)smraw;        // [64 d][QS] (d,i)
    __nv_bfloat16* Ql = Qh + 64*QS;
    __nv_bfloat16* Kh = Ql + 64*QS;                   // [64 d][QS] (d,j)
    __nv_bfloat16* Kl = Kh + 64*QS;
    __nv_bfloat16* Vh = Kl + 64*QS;                   // [64 d][QS] (d,j)
    __nv_bfloat16* Vl = Vh + 64*QS;
    float* sQRK  = (float*)(Vl + 64*QS);              // [64 i][9]
    float* sRK   = sQRK + 64*RNUM;                    // [9][64]
    float* sRV   = sRK + RNUM*64;                     // [9][64]
    float* sPB   = sRV + RNUM*64;                     // [64 i][12]
    float* sMask = sPB + 64*12;                       // [64]
    float* sO    = (float*)Kh;                        // [64 d][68] fp32, reuses K tiles at end

    int tid = threadIdx.x;
    int l = tid & 31, w = tid >> 5;
    int r = l >> 2;             // fragment row within 8
    int c2 = (l & 3) * 2;       // fragment col pair base
    int i0 = blockIdx.x * 64;
    int h  = blockIdx.y;
    int b  = blockIdx.z;
    const size_t hb = ((size_t)b*CC + h*HDD) * TT;

    // load Q tile (64d x 64i) -> split bf16 [d][i]
    #pragma unroll
    for (int p = 0; p < 8; p++) {
        int d  = (tid >> 4) + p*8;
        int iv = (tid & 15) * 4;
        float4 a4 = *(const float4*)&q[hb + (size_t)d*TT + i0 + iv];
        __nv_bfloat16 h0,l0,h1,l1,h2,l2,h3,l3;
        split_bf16(a4.x,h0,l0); split_bf16(a4.y,h1,l1);
        split_bf16(a4.z,h2,l2); split_bf16(a4.w,h3,l3);
        *(__nv_bfloat162*)&Qh[d*QS+iv]   = __nv_bfloat162(h0,h1);
        *(__nv_bfloat162*)&Qh[d*QS+iv+2] = __nv_bfloat162(h2,h3);
        *(__nv_bfloat162*)&Ql[d*QS+iv]   = __nv_bfloat162(l0,l1);
        *(__nv_bfloat162*)&Ql[d*QS+iv+2] = __nv_bfloat162(l2,l3);
    }
    for (int idx = tid; idx < RNUM*64; idx += 128) { sRK[idx] = relk[idx]; sRV[idx] = relv[idx]; }
    __syncthreads();

    // precompute q . rel_k : [64 i][9]
    for (int idx = tid; idx < 64*RNUM; idx += 128) {
        int ii = idx / RNUM, rr = idx % RNUM;
        float s = 0.f;
        #pragma unroll 8
        for (int d = 0; d < 64; d++)
            s += (__bfloat162float(Qh[d*QS+ii]) + __bfloat162float(Ql[d*QS+ii])) * sRK[rr*64 + d];
        sQRK[idx] = s;
    }
    __syncthreads();

    float accO[8][4];
    #pragma unroll
    for (int nb=0;nb<8;nb++)
        #pragma unroll
        for (int e=0;e<4;e++) accO[nb][e]=0.f;
    float mrun0=-1e30f, mrun1=-1e30f, lrun0=0.f, lrun1=0.f;

    for (int jt = 0; jt < TT/64; jt++) {
        int j0t = jt*64;
        // zero band buffer (own warp rows)
        for (int idx = l; idx < 16*12; idx += 32) sPB[(w*16 + idx/12)*12 + (idx%12)] = 0.f;
        // load K,V tiles -> split bf16 [d][j]
        #pragma unroll
        for (int p=0;p<8;p++){
            int d  = (tid>>4) + p*8;
            int jv = (tid&15)*4;
            float4 kk = *(const float4*)&k[hb + (size_t)d*TT + j0t + jv];
            float4 vv = *(const float4*)&v[hb + (size_t)d*TT + j0t + jv];
            __nv_bfloat16 h0,l0,h1,l1,h2,l2,h3,l3;
            split_bf16(kk.x,h0,l0); split_bf16(kk.y,h1,l1);
            split_bf16(kk.z,h2,l2); split_bf16(kk.w,h3,l3);
            *(__nv_bfloat162*)&Kh[d*QS+jv]   = __nv_bfloat162(h0,h1);
            *(__nv_bfloat162*)&Kh[d*QS+jv+2] = __nv_bfloat162(h2,h3);
            *(__nv_bfloat162*)&Kl[d*QS+jv]   = __nv_bfloat162(l0,l1);
            *(__nv_bfloat162*)&Kl[d*QS+jv+2] = __nv_bfloat162(l2,l3);
            split_bf16(vv.x,h0,l0); split_bf16(vv.y,h1,l1);
            split_bf16(vv.z,h2,l2); split_bf16(vv.w,h3,l3);
            *(__nv_bfloat162*)&Vh[d*QS+jv]   = __nv_bfloat162(h0,h1);
            *(__nv_bfloat162*)&Vh[d*QS+jv+2] = __nv_bfloat162(h2,h3);
            *(__nv_bfloat162*)&Vl[d*QS+jv]   = __nv_bfloat162(l0,l1);
            *(__nv_bfloat162*)&Vl[d*QS+jv+2] = __nv_bfloat162(l2,l3);
        }
        if (tid < 64) sMask[tid] = mask[(size_t)b*TT + j0t + tid];
        __syncthreads();

        // ---- S = Q K^T (3-pass split), warp: 16 i x 64 j ----
        float S[8][4];
        #pragma unroll
        for (int nb=0;nb<8;nb++)
            #pragma unroll
            for (int e=0;e<4;e++) S[nb][e]=0.f;
        #pragma unroll
        for (int ks=0; ks<4; ks++){
            int d0 = ks*16;
            unsigned Ah[4], Al[4];
            // A (Q): ldmatrix.x4.trans on [d][i]
            {
                int row = d0 + ((l>>4)&1)*8 + (l&7);
                int col = w*16 + ((l>>3)&1)*8;
                ldsm4t(Ah, &Qh[row*QS + col]);
                ldsm4t(Al, &Ql[row*QS + col]);
            }
            #pragma unroll
            for (int nbp=0; nbp<4; nbp++){
                unsigned Bh[4], Bl[4];
                // B (K): ldmatrix.x4.trans on [d][j], 2 n-blocks
                int row = d0 + ((l>>3)&1)*8 + (l&7);
                int col = nbp*16 + ((l>>4)&1)*8;
                ldsm4t(Bh, &Kh[row*QS + col]);
                ldsm4t(Bl, &Kl[row*QS + col]);
                mma16816(S[2*nbp],   Ah, &Bh[0]);
                mma16816(S[2*nbp],   Al, &Bh[0]);
                mma16816(S[2*nbp],   Ah, &Bl[0]);
                mma16816(S[2*nbp+1], Ah, &Bh[2]);
                mma16816(S[2*nbp+1], Al, &Bh[2]);
                mma16816(S[2*nbp+1], Ah, &Bl[2]);
            }
        }

        // ---- rel-k band + mask on fragments ----
        #pragma unroll
        for (int nb=0;nb<8;nb++){
            #pragma unroll
            for (int e=0;e<4;e++){
                int iloc = w*16 + r + ((e&2)?8:0);
                int jloc = nb*8 + c2 + (e&1);
                int delta = (j0t + jloc) - (i0 + iloc);
                if (delta >= -WW && delta <= WW) S[nb][e] += sQRK[iloc*RNUM + delta + WW];
                if (sMask[jloc] == 0.f) S[nb][e] = -1e30f;
            }
        }

        // ---- online softmax (rows r and r+8 of warp block) ----
        float tm0 = -1e30f, tm1 = -1e30f;
        #pragma unroll
        for (int nb=0;nb<8;nb++){
            tm0 = fmaxf(tm0, fmaxf(S[nb][0], S[nb][1]));
            tm1 = fmaxf(tm1, fmaxf(S[nb][2], S[nb][3]));
        }
        tm0 = fmaxf(tm0, __shfl_xor_sync(0xffffffffu, tm0, 1));
        tm0 = fmaxf(tm0, __shfl_xor_sync(0xffffffffu, tm0, 2));
        tm1 = fmaxf(tm1, __shfl_xor_sync(0xffffffffu, tm1, 1));
        tm1 = fmaxf(tm1, __shfl_xor_sync(0xffffffffu, tm1, 2));
        float mn0 = fmaxf(mrun0, tm0), mn1 = fmaxf(mrun1, tm1);
        float co0 = __expf(mrun0 - mn0), co1 = __expf(mrun1 - mn1);
        float rs0 = 0.f, rs1 = 0.f;
        #pragma unroll
        for (int nb=0;nb<8;nb++){
            S[nb][0] = __expf(S[nb][0]-mn0); rs0 += S[nb][0];
            S[nb][1] = __expf(S[nb][1]-mn0); rs0 += S[nb][1];
            S[nb][2] = __expf(S[nb][2]-mn1); rs1 += S[nb][2];
            S[nb][3] = __expf(S[nb][3]-mn1); rs1 += S[nb][3];
        }
        rs0 += __shfl_xor_sync(0xffffffffu, rs0, 1);
        rs0 += __shfl_xor_sync(0xffffffffu, rs0, 2);
        rs1 += __shfl_xor_sync(0xffffffffu, rs1, 1);
        rs1 += __shfl_xor_sync(0xffffffffu, rs1, 2);
        lrun0 = lrun0*co0 + rs0; mrun0 = mn0;
        lrun1 = lrun1*co1 + rs1; mrun1 = mn1;
        #pragma unroll
        for (int nb=0;nb<8;nb++){
            accO[nb][0]*=co0; accO[nb][1]*=co0;
            accO[nb][2]*=co1; accO[nb][3]*=co1;
        }

        // ---- band P -> sPB (warp-local) ----
        #pragma unroll
        for (int nb=0;nb<8;nb++){
            #pragma unroll
            for (int e=0;e<4;e++){
                int iloc = w*16 + r + ((e&2)?8:0);
                int jloc = nb*8 + c2 + (e&1);
                int delta = (j0t + jloc) - (i0 + iloc);
                if (delta >= -WW && delta <= WW) sPB[iloc*12 + delta + WW] = S[nb][e];
            }
        }
        __syncwarp();

        // ---- O += P V (3-pass split) ----
        #pragma unroll
        for (int s=0; s<4; s++){
            unsigned Ph[4], Pl[4];
            split_pack2(S[2*s][0],   S[2*s][1],   Ph[0], Pl[0]);
            split_pack2(S[2*s][2],   S[2*s][3],   Ph[1], Pl[1]);
            split_pack2(S[2*s+1][0], S[2*s+1][1], Ph[2], Pl[2]);
            split_pack2(S[2*s+1][2], S[2*s+1][3], Ph[3], Pl[3]);
            #pragma unroll
            for (int dp=0; dp<4; dp++){
                unsigned Bh[4], Bl[4];
                // B (V): ldmatrix.x4 non-trans on [d][j], 2 d n-blocks
                int row = dp*16 + ((l>>4)&1)*8 + (l&7);
                int col = s*16 + ((l>>3)&1)*8;
                ldsm4(Bh, &Vh[row*QS + col]);
                ldsm4(Bl, &Vl[row*QS + col]);
                mma16816(accO[2*dp],   Ph, &Bh[0]);
                mma16816(accO[2*dp],   Pl, &Bh[0]);
                mma16816(accO[2*dp],   Ph, &Bl[0]);
                mma16816(accO[2*dp+1], Ph, &Bh[2]);
                mma16816(accO[2*dp+1], Pl, &Bh[2]);
                mma16816(accO[2*dp+1], Ph, &Bl[2]);
            }
        }

        // ---- O += P_band * rel_v ----
        {
            int r0i = (w*16 + r)*12, r1i = (w*16 + r + 8)*12;
            #pragma unroll
            for (int t=0; t<RNUM; t++){
                float pb0 = sPB[r0i + t];
                float pb1 = sPB[r1i + t];
                #pragma unroll
                for (int nb=0;nb<8;nb++){
                    int d0 = nb*8 + c2;
                    float rv0 = sRV[t*64 + d0];
                    float rv1 = sRV[t*64 + d0 + 1];
                    accO[nb][0] += pb0*rv0; accO[nb][1] += pb0*rv1;
                    accO[nb][2] += pb1*rv0; accO[nb][3] += pb1*rv1;
                }
            }
        }
        __syncthreads();
    }

    // ---- normalize, stage [d][i] in smem, coalesced write ----
    float inv0 = 1.f / lrun0, inv1 = 1.f / lrun1;
    #pragma unroll
    for (int nb=0;nb<8;nb++){
        #pragma unroll
        for (int e=0;e<4;e++){
            int iloc = w*16 + r + ((e&2)?8:0);
            int d = nb*8 + c2 + (e&1);
            sO[d*68 + iloc] = accO[nb][e] * ((e&2)?inv1:inv0);
        }
    }
    __syncthreads();
    #pragma unroll
    for (int p=0;p<8;p++){
        int d  = (tid>>4) + p*8;
        int iv = (tid&15)*4;
        *(float4*)&o[hb + (size_t)d*TT + i0 + iv] = *(const float4*)&sO[d*68 + iv];
    }
}

// ---------------- fused residual + LayerNorm over C (+optional mask) ----------------
__global__ void __launch_bounds__(256) add_ln_kernel(
    const float* __restrict__ res, const float* __restrict__ y,
    const float* __restrict__ g, const float* __restrict__ beta,
    const float* __restrict__ mask, int use_mask, float* __restrict__ dst)
{
    __shared__ float sS[8][32], sS2[8][32];
    int b  = blockIdx.y;
    int tt = threadIdx.x & 31;
    int cg = threadIdx.x >> 5;
    int t  = blockIdx.x*32 + tt;
    size_t base = (size_t)b*CC*TT + t;
    float s=0.f, s2=0.f;
    for (int c=cg; c<CC; c+=8){
        float vv = res[base + (size_t)c*TT] + y[base + (size_t)c*TT];
        s += vv; s2 += vv*vv;
    }
    sS[cg][tt]=s; sS2[cg][tt]=s2;
    __syncthreads();
    if (cg==0){
        #pragma unroll
        for (int i=1;i<8;i++){ s += sS[i][tt]; s2 += sS2[i][tt]; }
        float mean = s * (1.f/CC);
        float var  = s2 * (1.f/CC) - mean*mean;
        sS[0][tt]  = mean;
        sS2[0][tt] = rsqrtf(var + 1e-6f);
    }
    __syncthreads();
    float mean = sS[0][tt], inv = sS2[0][tt];
    float mk = use_mask ? mask[(size_t)b*TT + t] : 1.f;
    for (int c=cg; c<CC; c+=8){
        float vv  = res[base + (size_t)c*TT] + y[base + (size_t)c*TT];
        float ovv = (vv-mean)*inv*g[c] + beta[c];
        dst[base + (size_t)c*TT] = ovv*mk;
    }
}

#define ATTN_SMEM_BYTES 65536

extern "C" void kernel_launch(void* const* d_in, const int* in_sizes, int n_in,
                              void* d_out, int out_size)
{
    const float* x    = (const float*)d_in[0];
    const float* mask = (const float*)d_in[1];
    const float* qw   = (const float*)d_in[2];
    const float* qb   = (const float*)d_in[3];
    const float* kw   = (const float*)d_in[4];
    const float* kb   = (const float*)d_in[5];
    const float* vw   = (const float*)d_in[6];
    const float* vb   = (const float*)d_in[7];
    const float* ow   = (const float*)d_in[8];
    const float* ob   = (const float*)d_in[9];
    const float* rk   = (const float*)d_in[10];
    const float* rv   = (const float*)d_in[11];
    const float* ln1g = (const float*)d_in[12];
    const float* ln1b = (const float*)d_in[13];
    const float* w1   = (const float*)d_in[14];
    const float* b1   = (const float*)d_in[15];
    const float* w2   = (const float*)d_in[16];
    const float* b2   = (const float*)d_in[17];
    const float* ln2g = (const float*)d_in[18];
    const float* ln2b = (const float*)d_in[19];

    float *gx,*gq,*gk,*gv,*go,*gt,*gh;
    cudaGetSymbolAddress((void**)&gx, g_x);
    cudaGetSymbolAddress((void**)&gq, g_q);
    cudaGetSymbolAddress((void**)&gk, g_k);
    cudaGetSymbolAddress((void**)&gv, g_v);
    cudaGetSymbolAddress((void**)&go, g_o);
    cudaGetSymbolAddress((void**)&gt, g_t);
    cudaGetSymbolAddress((void**)&gh, g_h);

    cudaFuncSetAttribute(attn_mma_kernel, cudaFuncAttributeMaxDynamicSharedMemorySize, ATTN_SMEM_BYTES);

    cudaMemcpyAsync(gx, x, sizeof(float)*BB*CC*TT, cudaMemcpyDeviceToDevice, 0);

    const float inv_scale = 0.125f; // 1/sqrt(64)
    dim3 blk(256);
    for (int i=0;i<LL;i++){
        size_t wofs = (size_t)i*CC*CC;
        gemm_mma_kernel<0,0,0,1><<<dim3(TT/128, CC/128, BB), blk>>>(qw+wofs, gx, qb+i*CC, mask, gq, CC, TT, CC, inv_scale);
        gemm_mma_kernel<0,0,0,0><<<dim3(TT/128, CC/128, BB), blk>>>(kw+wofs, gx, kb+i*CC, mask, gk, CC, TT, CC, 1.f);
        gemm_mma_kernel<0,0,0,0><<<dim3(TT/128, CC/128, BB), blk>>>(vw+wofs, gx, vb+i*CC, mask, gv, CC, TT, CC, 1.f);
        attn_mma_kernel<<<dim3(TT/64, HH, BB), dim3(128), ATTN_SMEM_BYTES>>>(gq, gk, gv,
            rk + (size_t)i*RNUM*HDD, rv + (size_t)i*RNUM*HDD, mask, go);
        gemm_mma_kernel<0,0,0,0><<<dim3(TT/128, CC/128, BB), blk>>>(ow+wofs, go, ob+i*CC, mask, gt, CC, TT, CC, 1.f);
        add_ln_kernel<<<dim3(TT/32, BB), blk>>>(gx, gt, ln1g+i*CC, ln1b+i*CC, mask, 0, gx);
        gemm_mma_kernel<1,1,1,0><<<dim3(TT/128, FF/128, BB), blk>>>(w1+(size_t)i*FF*CC, gx, b1+i*FF, mask, gh, FF, TT, CC, 1.f);
        gemm_mma_kernel<0,0,1,0><<<dim3(TT/128, CC/128, BB), blk>>>(w2+(size_t)i*CC*FF, gh, b2+i*CC, mask, gt, CC, TT, FF, 1.f);
        float* dst = (i==LL-1) ? (float*)d_out : gx;
        add_ln_kernel<<<dim3(TT/32, BB), blk>>>(gx, gt, ln2g+i*CC, ln2b+i*CC, mask, 1, dst);
    }
}

// round 4
// speedup vs baseline: 2.1883x; 1.1043x over previous
#include <cuda_runtime.h>
#include <cuda_bf16.h>
#include <math.h>

#define BB 4
#define CC 512
#define TT 1024
#define HH 8
#define HDD 64
#define FF 2048
#define LL 4
#define WW 4
#define RNUM 9

// ---------------- scratch (no allocations allowed) ----------------
__device__ float g_x[BB*CC*TT];          // fp32 residual / layer state
__device__ float g_t[BB*CC*TT];          // fp32 gemm output (pre-LN)
// split-bf16 activations
__device__ __nv_bfloat16 g_xh[BB*CC*TT], g_xl[BB*CC*TT];
__device__ __nv_bfloat16 g_qh[BB*CC*TT], g_ql[BB*CC*TT];
__device__ __nv_bfloat16 g_kh[BB*CC*TT], g_kl[BB*CC*TT];
__device__ __nv_bfloat16 g_vh[BB*CC*TT], g_vl[BB*CC*TT];
__device__ __nv_bfloat16 g_oh[BB*CC*TT], g_ol[BB*CC*TT];
__device__ __nv_bfloat16 g_hh[BB*FF*TT], g_hl[BB*FF*TT];
// split-bf16 weights (all layers)
__device__ __nv_bfloat16 g_wqh[LL*CC*CC], g_wql[LL*CC*CC];
__device__ __nv_bfloat16 g_wkh[LL*CC*CC], g_wkl[LL*CC*CC];
__device__ __nv_bfloat16 g_wvh[LL*CC*CC], g_wvl[LL*CC*CC];
__device__ __nv_bfloat16 g_woh[LL*CC*CC], g_wol[LL*CC*CC];
__device__ __nv_bfloat16 g_w1h[LL*FF*CC], g_w1l[LL*FF*CC];
__device__ __nv_bfloat16 g_w2h[LL*CC*FF], g_w2l[LL*CC*FF];

// ---------------- helpers ----------------
__device__ __forceinline__ void mma16816(float* d, const unsigned* a, const unsigned* b){
    asm volatile("mma.sync.aligned.m16n8k16.row.col.f32.bf16.bf16.f32 "
        "{%0,%1,%2,%3}, {%4,%5,%6,%7}, {%8,%9}, {%0,%1,%2,%3};"
        : "+f"(d[0]),"+f"(d[1]),"+f"(d[2]),"+f"(d[3])
        : "r"(a[0]),"r"(a[1]),"r"(a[2]),"r"(a[3]), "r"(b[0]),"r"(b[1]));
}
__device__ __forceinline__ void ldsm4(unsigned* r, const void* p){
    unsigned addr = (unsigned)__cvta_generic_to_shared(p);
    asm volatile("ldmatrix.sync.aligned.m8n8.x4.shared.b16 {%0,%1,%2,%3}, [%4];"
        : "=r"(r[0]),"=r"(r[1]),"=r"(r[2]),"=r"(r[3]) : "r"(addr));
}
__device__ __forceinline__ void ldsm4t(unsigned* r, const void* p){
    unsigned addr = (unsigned)__cvta_generic_to_shared(p);
    asm volatile("ldmatrix.sync.aligned.m8n8.x4.trans.shared.b16 {%0,%1,%2,%3}, [%4];"
        : "=r"(r[0]),"=r"(r[1]),"=r"(r[2]),"=r"(r[3]) : "r"(addr));
}
__device__ __forceinline__ void ldsm2t(unsigned* r, const void* p){
    unsigned addr = (unsigned)__cvta_generic_to_shared(p);
    asm volatile("ldmatrix.sync.aligned.m8n8.x2.trans.shared.b16 {%0,%1}, [%2];"
        : "=r"(r[0]),"=r"(r[1]) : "r"(addr));
}
__device__ __forceinline__ void split_bf16(float v, __nv_bfloat16& h, __nv_bfloat16& l){
    h = __float2bfloat16(v);
    l = __float2bfloat16(v - __bfloat162float(h));
}
__device__ __forceinline__ void split_pack2(float x, float y, unsigned& hp, unsigned& lp){
    __nv_bfloat16 hx, lx, hy, ly;
    split_bf16(x, hx, lx); split_bf16(y, hy, ly);
    __nv_bfloat162 th(hx, hy), tl(lx, ly);
    hp = *(unsigned*)&th; lp = *(unsigned*)&tl;
}
__device__ __forceinline__ void cpa16(void* s, const void* g){
    unsigned sa = (unsigned)__cvta_generic_to_shared(s);
    asm volatile("cp.async.cg.shared.global [%0], [%1], 16;" :: "r"(sa), "l"(g));
}
__device__ __forceinline__ void cpcommit(){ asm volatile("cp.async.commit_group;"); }
template<int NN> __device__ __forceinline__ void cpwait(){ asm volatile("cp.async.wait_group %0;" :: "n"(NN)); }

// ---------------- split kernels (run once per launch) ----------------
__global__ void split_kernel(const float* __restrict__ in,
                             __nv_bfloat16* __restrict__ oh, __nv_bfloat16* __restrict__ ol, int n){
    int i = (blockIdx.x*blockDim.x + threadIdx.x)*4;
    if (i >= n) return;
    float4 v = *(const float4*)&in[i];
    __nv_bfloat16 h0,l0,h1,l1,h2,l2,h3,l3;
    split_bf16(v.x,h0,l0); split_bf16(v.y,h1,l1);
    split_bf16(v.z,h2,l2); split_bf16(v.w,h3,l3);
    *(__nv_bfloat162*)&oh[i]   = __nv_bfloat162(h0,h1);
    *(__nv_bfloat162*)&oh[i+2] = __nv_bfloat162(h2,h3);
    *(__nv_bfloat162*)&ol[i]   = __nv_bfloat162(l0,l1);
    *(__nv_bfloat162*)&ol[i+2] = __nv_bfloat162(l2,l3);
}
__global__ void split_copy_kernel(const float* __restrict__ in, float* __restrict__ of,
                                  __nv_bfloat16* __restrict__ oh, __nv_bfloat16* __restrict__ ol, int n){
    int i = (blockIdx.x*blockDim.x + threadIdx.x)*4;
    if (i >= n) return;
    float4 v = *(const float4*)&in[i];
    *(float4*)&of[i] = v;
    __nv_bfloat16 h0,l0,h1,l1,h2,l2,h3,l3;
    split_bf16(v.x,h0,l0); split_bf16(v.y,h1,l1);
    split_bf16(v.z,h2,l2); split_bf16(v.w,h3,l3);
    *(__nv_bfloat162*)&oh[i]   = __nv_bfloat162(h0,h1);
    *(__nv_bfloat162*)&oh[i+2] = __nv_bfloat162(h2,h3);
    *(__nv_bfloat162*)&ol[i]   = __nv_bfloat162(l0,l1);
    *(__nv_bfloat162*)&ol[i+2] = __nv_bfloat162(l2,l3);
}

// ---------------- bf16 split GEMM with cp.async double buffer ----------------
// out[b][m][n] = sum_k (Ah+Al)[m][k] (Bh+Bl)[b][k][n] (+bias, epilogue), 3-pass mma
template<int RELU, int MASK_OUT, int SPLIT_OUT, int DO_SCALE>
__global__ void __launch_bounds__(256,2) gemm_bf16_kernel(
    const __nv_bfloat16* __restrict__ Ah_g, const __nv_bfloat16* __restrict__ Al_g,
    const __nv_bfloat16* __restrict__ Bh_g, const __nv_bfloat16* __restrict__ Bl_g,
    const float* __restrict__ bias, const float* __restrict__ mask,
    float* __restrict__ outF, __nv_bfloat16* __restrict__ outH, __nv_bfloat16* __restrict__ outL,
    int M, int N, int K, float scale)
{
    __shared__ __nv_bfloat16 As_h[2][128][40];
    __shared__ __nv_bfloat16 As_l[2][128][40];
    __shared__ __nv_bfloat16 Bs_h[2][32][136];
    __shared__ __nv_bfloat16 Bs_l[2][32][136];

    int b = blockIdx.z;
    const __nv_bfloat16* Bh_b = Bh_g + (size_t)b*K*N;
    const __nv_bfloat16* Bl_b = Bl_g + (size_t)b*K*N;
    int m0 = blockIdx.y*128, n0 = blockIdx.x*128;
    int tid = threadIdx.x;
    int l = tid & 31, w = tid >> 5;
    int wm0 = (w >> 2) * 64;
    int wn0 = (w & 3) * 32;

    float acc[4][4][4];
    #pragma unroll
    for (int mi=0;mi<4;mi++)
        #pragma unroll
        for (int ni=0;ni<4;ni++)
            #pragma unroll
            for (int e=0;e<4;e++) acc[mi][ni][e]=0.f;

    int nt = K/32;
    // stage loader
    auto load_stage = [&](int it, int buf){
        int k0 = it*32;
        #pragma unroll
        for (int p=0;p<2;p++){
            int c = tid + p*256;
            int row = c>>2, col8 = (c&3)*8;
            size_t go = (size_t)(m0+row)*K + k0 + col8;
            cpa16(&As_h[buf][row][col8], Ah_g + go);
            cpa16(&As_l[buf][row][col8], Al_g + go);
        }
        #pragma unroll
        for (int p=0;p<2;p++){
            int c = tid + p*256;
            int row = c>>4, col8 = (c&15)*8;
            size_t go = (size_t)(k0+row)*N + n0 + col8;
            cpa16(&Bs_h[buf][row][col8], Bh_b + go);
            cpa16(&Bs_l[buf][row][col8], Bl_b + go);
        }
    };

    load_stage(0,0); cpcommit();

    for (int it=0; it<nt; ++it){
        int buf = it & 1;
        if (it+1 < nt){ load_stage(it+1, buf^1); cpcommit(); cpwait<1>(); }
        else cpwait<0>();
        __syncthreads();

        #pragma unroll
        for (int ks=0; ks<32; ks+=16){
            unsigned Bh[4][2], Bl[4][2];
            #pragma unroll
            for (int ni=0;ni<4;ni++){
                ldsm2t(Bh[ni], &Bs_h[buf][ks + (l & 15)][wn0 + ni*8]);
                ldsm2t(Bl[ni], &Bs_l[buf][ks + (l & 15)][wn0 + ni*8]);
            }
            #pragma unroll
            for (int mi=0;mi<4;mi++){
                unsigned Ah[4], Al[4];
                ldsm4(Ah, &As_h[buf][wm0 + mi*16 + (l & 15)][ks + (l >> 4)*8]);
                ldsm4(Al, &As_l[buf][wm0 + mi*16 + (l & 15)][ks + (l >> 4)*8]);
                #pragma unroll
                for (int ni=0;ni<4;ni++){
                    mma16816(acc[mi][ni], Ah, Bh[ni]);
                    mma16816(acc[mi][ni], Al, Bh[ni]);
                    mma16816(acc[mi][ni], Ah, Bl[ni]);
                }
            }
        }
        __syncthreads();
    }

    // epilogue
    #pragma unroll
    for (int mi=0;mi<4;mi++){
        int r = m0 + wm0 + mi*16 + (l >> 2);
        float bv0 = bias[r], bv1 = bias[r+8];
        #pragma unroll
        for (int ni=0;ni<4;ni++){
            int cn = n0 + wn0 + ni*8 + (l & 3)*2;
            float m00=1.f, m01=1.f;
            if (MASK_OUT){
                m00 = mask[(size_t)b*TT + cn];
                m01 = mask[(size_t)b*TT + cn + 1];
            }
            float c0 = acc[mi][ni][0] + bv0;
            float c1 = acc[mi][ni][1] + bv0;
            float c2 = acc[mi][ni][2] + bv1;
            float c3 = acc[mi][ni][3] + bv1;
            if (DO_SCALE){ c0*=scale; c1*=scale; c2*=scale; c3*=scale; }
            if (RELU){ c0=fmaxf(c0,0.f); c1=fmaxf(c1,0.f); c2=fmaxf(c2,0.f); c3=fmaxf(c3,0.f); }
            if (MASK_OUT){ c0*=m00; c1*=m01; c2*=m00; c3*=m01; }
            if (SPLIT_OUT){
                size_t base = (size_t)b*M*N;
                __nv_bfloat16 h0,l0,h1,l1;
                split_bf16(c0,h0,l0); split_bf16(c1,h1,l1);
                *(__nv_bfloat162*)&outH[base + (size_t)r*N + cn] = __nv_bfloat162(h0,h1);
                *(__nv_bfloat162*)&outL[base + (size_t)r*N + cn] = __nv_bfloat162(l0,l1);
                split_bf16(c2,h0,l0); split_bf16(c3,h1,l1);
                *(__nv_bfloat162*)&outH[base + (size_t)(r+8)*N + cn] = __nv_bfloat162(h0,h1);
                *(__nv_bfloat162*)&outL[base + (size_t)(r+8)*N + cn] = __nv_bfloat162(l0,l1);
            } else {
                size_t base = (size_t)b*M*N;
                *(float2*)&outF[base + (size_t)r*N + cn]     = make_float2(c0,c1);
                *(float2*)&outF[base + (size_t)(r+8)*N + cn] = make_float2(c2,c3);
            }
        }
    }
}

// ---------------- tensor-core flash attention, pre-split inputs ----------------
// grid (T/64, H, B), 128 threads (4 warps). q/k/v/o all split bf16 in (B,C,T).
#define KQS 72
__global__ void __launch_bounds__(128) attn_mma_kernel(
    const __nv_bfloat16* __restrict__ qh, const __nv_bfloat16* __restrict__ ql,
    const __nv_bfloat16* __restrict__ kh, const __nv_bfloat16* __restrict__ kl,
    const __nv_bfloat16* __restrict__ vh, const __nv_bfloat16* __restrict__ vl,
    const float* __restrict__ relk, const float* __restrict__ relv,
    const float* __restrict__ mask,
    __nv_bfloat16* __restrict__ oh, __nv_bfloat16* __restrict__ ol)
{
    extern __shared__ char smraw[];
    __nv_bfloat16* Qh = (__nv_bfloat16*)smraw;        // [64 d][72] (d,i)
    __nv_bfloat16* Ql = Qh + 64*KQS;
    __nv_bfloat16* Kh = Ql + 64*KQS;                  // [64 d][72] (d,j)
    __nv_bfloat16* Kl = Kh + 64*KQS;
    __nv_bfloat16* Vh = Kl + 64*KQS;                  // [64 d][72] (d,j)
    __nv_bfloat16* Vl = Vh + 64*KQS;
    float* sQRK  = (float*)(Vl + 64*KQS);             // [64 i][9]
    float* sRK   = sQRK + 64*RNUM;                    // [9][64]
    float* sRV   = sRK + RNUM*64;                     // [9][64]
    float* sPB   = sRV + RNUM*64;                     // [64 i][12]
    float* sMask = sPB + 64*12;                       // [64]
    float* sO    = (float*)Kh;                        // [64 d][68] fp32 out stage (overlays K)

    int tid = threadIdx.x;
    int l = tid & 31, w = tid >> 5;
    int r = l >> 2;
    int c2 = (l & 3) * 2;
    int i0 = blockIdx.x * 64;
    int h  = blockIdx.y;
    int b  = blockIdx.z;
    const size_t hb = ((size_t)b*CC + h*HDD) * TT;

    // Q tiles via cp.async (64 rows x 8 chunks of 8 bf16, per buffer)
    #pragma unroll
    for (int p=0;p<4;p++){
        int c = tid + p*128;
        int row = c>>3, col8 = (c&7)*8;
        size_t go = hb + (size_t)row*TT + i0 + col8;
        cpa16(&Qh[row*KQS + col8], qh + go);
        cpa16(&Ql[row*KQS + col8], ql + go);
    }
    cpcommit();
    for (int idx = tid; idx < RNUM*64; idx += 128) { sRK[idx] = relk[idx]; sRV[idx] = relv[idx]; }
    cpwait<0>();
    __syncthreads();

    // precompute q . rel_k : [64 i][9]
    for (int idx = tid; idx < 64*RNUM; idx += 128) {
        int ii = idx / RNUM, rr = idx % RNUM;
        float s = 0.f;
        #pragma unroll 8
        for (int d = 0; d < 64; d++)
            s += (__bfloat162float(Qh[d*KQS+ii]) + __bfloat162float(Ql[d*KQS+ii])) * sRK[rr*64 + d];
        sQRK[idx] = s;
    }
    __syncthreads();

    float accO[8][4];
    #pragma unroll
    for (int nb=0;nb<8;nb++)
        #pragma unroll
        for (int e=0;e<4;e++) accO[nb][e]=0.f;
    float mrun0=-1e30f, mrun1=-1e30f, lrun0=0.f, lrun1=0.f;

    for (int jt = 0; jt < TT/64; jt++) {
        int j0t = jt*64;
        // K,V tiles via cp.async
        #pragma unroll
        for (int p=0;p<4;p++){
            int c = tid + p*128;
            int row = c>>3, col8 = (c&7)*8;
            size_t go = hb + (size_t)row*TT + j0t + col8;
            cpa16(&Kh[row*KQS + col8], kh + go);
            cpa16(&Kl[row*KQS + col8], kl + go);
            cpa16(&Vh[row*KQS + col8], vh + go);
            cpa16(&Vl[row*KQS + col8], vl + go);
        }
        cpcommit();
        // zero band buffer (own warp rows)
        for (int idx = l; idx < 16*12; idx += 32) sPB[(w*16 + idx/12)*12 + (idx%12)] = 0.f;
        if (tid < 64) sMask[tid] = mask[(size_t)b*TT + j0t + tid];
        cpwait<0>();
        __syncthreads();

        // ---- S = Q K^T (3-pass split) ----
        float S[8][4];
        #pragma unroll
        for (int nb=0;nb<8;nb++)
            #pragma unroll
            for (int e=0;e<4;e++) S[nb][e]=0.f;
        #pragma unroll
        for (int ks=0; ks<4; ks++){
            int d0 = ks*16;
            unsigned Ah[4], Al[4];
            {
                int row = d0 + ((l>>4)&1)*8 + (l&7);
                int col = w*16 + ((l>>3)&1)*8;
                ldsm4t(Ah, &Qh[row*KQS + col]);
                ldsm4t(Al, &Ql[row*KQS + col]);
            }
            #pragma unroll
            for (int nbp=0; nbp<4; nbp++){
                unsigned Bh[4], Bl[4];
                int row = d0 + ((l>>3)&1)*8 + (l&7);
                int col = nbp*16 + ((l>>4)&1)*8;
                ldsm4t(Bh, &Kh[row*KQS + col]);
                ldsm4t(Bl, &Kl[row*KQS + col]);
                mma16816(S[2*nbp],   Ah, &Bh[0]);
                mma16816(S[2*nbp],   Al, &Bh[0]);
                mma16816(S[2*nbp],   Ah, &Bl[0]);
                mma16816(S[2*nbp+1], Ah, &Bh[2]);
                mma16816(S[2*nbp+1], Al, &Bh[2]);
                mma16816(S[2*nbp+1], Ah, &Bl[2]);
            }
        }

        // ---- rel-k band + mask ----
        #pragma unroll
        for (int nb=0;nb<8;nb++){
            #pragma unroll
            for (int e=0;e<4;e++){
                int iloc = w*16 + r + ((e&2)?8:0);
                int jloc = nb*8 + c2 + (e&1);
                int delta = (j0t + jloc) - (i0 + iloc);
                if (delta >= -WW && delta <= WW) S[nb][e] += sQRK[iloc*RNUM + delta + WW];
                if (sMask[jloc] == 0.f) S[nb][e] = -1e30f;
            }
        }

        // ---- online softmax ----
        float tm0 = -1e30f, tm1 = -1e30f;
        #pragma unroll
        for (int nb=0;nb<8;nb++){
            tm0 = fmaxf(tm0, fmaxf(S[nb][0], S[nb][1]));
            tm1 = fmaxf(tm1, fmaxf(S[nb][2], S[nb][3]));
        }
        tm0 = fmaxf(tm0, __shfl_xor_sync(0xffffffffu, tm0, 1));
        tm0 = fmaxf(tm0, __shfl_xor_sync(0xffffffffu, tm0, 2));
        tm1 = fmaxf(tm1, __shfl_xor_sync(0xffffffffu, tm1, 1));
        tm1 = fmaxf(tm1, __shfl_xor_sync(0xffffffffu, tm1, 2));
        float mn0 = fmaxf(mrun0, tm0), mn1 = fmaxf(mrun1, tm1);
        float co0 = __expf(mrun0 - mn0), co1 = __expf(mrun1 - mn1);
        float rs0 = 0.f, rs1 = 0.f;
        #pragma unroll
        for (int nb=0;nb<8;nb++){
            S[nb][0] = __expf(S[nb][0]-mn0); rs0 += S[nb][0];
            S[nb][1] = __expf(S[nb][1]-mn0); rs0 += S[nb][1];
            S[nb][2] = __expf(S[nb][2]-mn1); rs1 += S[nb][2];
            S[nb][3] = __expf(S[nb][3]-mn1); rs1 += S[nb][3];
        }
        rs0 += __shfl_xor_sync(0xffffffffu, rs0, 1);
        rs0 += __shfl_xor_sync(0xffffffffu, rs0, 2);
        rs1 += __shfl_xor_sync(0xffffffffu, rs1, 1);
        rs1 += __shfl_xor_sync(0xffffffffu, rs1, 2);
        lrun0 = lrun0*co0 + rs0; mrun0 = mn0;
        lrun1 = lrun1*co1 + rs1; mrun1 = mn1;
        #pragma unroll
        for (int nb=0;nb<8;nb++){
            accO[nb][0]*=co0; accO[nb][1]*=co0;
            accO[nb][2]*=co1; accO[nb][3]*=co1;
        }

        // ---- band P -> sPB ----
        #pragma unroll
        for (int nb=0;nb<8;nb++){
            #pragma unroll
            for (int e=0;e<4;e++){
                int iloc = w*16 + r + ((e&2)?8:0);
                int jloc = nb*8 + c2 + (e&1);
                int delta = (j0t + jloc) - (i0 + iloc);
                if (delta >= -WW && delta <= WW) sPB[iloc*12 + delta + WW] = S[nb][e];
            }
        }
        __syncwarp();

        // ---- O += P V (3-pass split) ----
        #pragma unroll
        for (int s=0; s<4; s++){
            unsigned Ph[4], Pl[4];
            split_pack2(S[2*s][0],   S[2*s][1],   Ph[0], Pl[0]);
            split_pack2(S[2*s][2],   S[2*s][3],   Ph[1], Pl[1]);
            split_pack2(S[2*s+1][0], S[2*s+1][1], Ph[2], Pl[2]);
            split_pack2(S[2*s+1][2], S[2*s+1][3], Ph[3], Pl[3]);
            #pragma unroll
            for (int dp=0; dp<4; dp++){
                unsigned Bh[4], Bl[4];
                int row = dp*16 + ((l>>4)&1)*8 + (l&7);
                int col = s*16 + ((l>>3)&1)*8;
                ldsm4(Bh, &Vh[row*KQS + col]);
                ldsm4(Bl, &Vl[row*KQS + col]);
                mma16816(accO[2*dp],   Ph, &Bh[0]);
                mma16816(accO[2*dp],   Pl, &Bh[0]);
                mma16816(accO[2*dp],   Ph, &Bl[0]);
                mma16816(accO[2*dp+1], Ph, &Bh[2]);
                mma16816(accO[2*dp+1], Pl, &Bh[2]);
                mma16816(accO[2*dp+1], Ph, &Bl[2]);
            }
        }

        // ---- O += P_band * rel_v ----
        {
            int r0i = (w*16 + r)*12, r1i = (w*16 + r + 8)*12;
            #pragma unroll
            for (int t=0; t<RNUM; t++){
                float pb0 = sPB[r0i + t];
                float pb1 = sPB[r1i + t];
                #pragma unroll
                for (int nb=0;nb<8;nb++){
                    int d0 = nb*8 + c2;
                    float rv0 = sRV[t*64 + d0];
                    float rv1 = sRV[t*64 + d0 + 1];
                    accO[nb][0] += pb0*rv0; accO[nb][1] += pb0*rv1;
                    accO[nb][2] += pb1*rv0; accO[nb][3] += pb1*rv1;
                }
            }
        }
        __syncthreads();
    }

    // ---- normalize, stage fp32 [d][i], split-write to oh/ol ----
    float inv0 = 1.f / lrun0, inv1 = 1.f / lrun1;
    #pragma unroll
    for (int nb=0;nb<8;nb++){
        #pragma unroll
        for (int e=0;e<4;e++){
            int iloc = w*16 + r + ((e&2)?8:0);
            int d = nb*8 + c2 + (e&1);
            sO[d*68 + iloc] = accO[nb][e] * ((e&2)?inv1:inv0);
        }
    }
    __syncthreads();
    #pragma unroll
    for (int p=0;p<4;p++){
        int c = tid + p*128;
        int row = c>>3, col8 = (c&7)*8;
        size_t go = hb + (size_t)row*TT + i0 + col8;
        #pragma unroll
        for (int j=0;j<8;j+=2){
            float v0 = sO[row*68 + col8 + j];
            float v1 = sO[row*68 + col8 + j + 1];
            __nv_bfloat16 h0,l0,h1,l1;
            split_bf16(v0,h0,l0); split_bf16(v1,h1,l1);
            *(__nv_bfloat162*)&oh[go + j] = __nv_bfloat162(h0,h1);
            *(__nv_bfloat162*)&ol[go + j] = __nv_bfloat162(l0,l1);
        }
    }
}

// ---------------- fused residual + LayerNorm; writes fp32 + split-bf16(masked) ----
__global__ void __launch_bounds__(256) add_ln_kernel(
    const float* __restrict__ res, const float* __restrict__ y,
    const float* __restrict__ g, const float* __restrict__ beta,
    const float* __restrict__ mask, int mask_f32, float* __restrict__ dst,
    __nv_bfloat16* __restrict__ dstH, __nv_bfloat16* __restrict__ dstL)
{
    __shared__ float sS[8][32], sS2[8][32];
    int b  = blockIdx.y;
    int tt = threadIdx.x & 31;
    int cg = threadIdx.x >> 5;
    int t  = blockIdx.x*32 + tt;
    size_t base = (size_t)b*CC*TT + t;
    float s=0.f, s2=0.f;
    for (int c=cg; c<CC; c+=8){
        float vv = res[base + (size_t)c*TT] + y[base + (size_t)c*TT];
        s += vv; s2 += vv*vv;
    }
    sS[cg][tt]=s; sS2[cg][tt]=s2;
    __syncthreads();
    if (cg==0){
        #pragma unroll
        for (int i=1;i<8;i++){ s += sS[i][tt]; s2 += sS2[i][tt]; }
        float mean = s * (1.f/CC);
        float var  = s2 * (1.f/CC) - mean*mean;
        sS[0][tt]  = mean;
        sS2[0][tt] = rsqrtf(var + 1e-6f);
    }
    __syncthreads();
    float mean = sS[0][tt], inv = sS2[0][tt];
    float mk = mask[(size_t)b*TT + t];
    float mkf = mask_f32 ? mk : 1.f;
    for (int c=cg; c<CC; c+=8){
        float vv  = res[base + (size_t)c*TT] + y[base + (size_t)c*TT];
        float ovv = (vv-mean)*inv*g[c] + beta[c];
        dst[base + (size_t)c*TT] = ovv*mkf;
        float mv = ovv*mk;
        __nv_bfloat16 hh, ll;
        split_bf16(mv, hh, ll);
        dstH[base + (size_t)c*TT] = hh;
        dstL[base + (size_t)c*TT] = ll;
    }
}

#define ATTN_SMEM_BYTES 65536

extern "C" void kernel_launch(void* const* d_in, const int* in_sizes, int n_in,
                              void* d_out, int out_size)
{
    const float* x    = (const float*)d_in[0];
    const float* mask = (const float*)d_in[1];
    const float* qw   = (const float*)d_in[2];
    const float* qb   = (const float*)d_in[3];
    const float* kw   = (const float*)d_in[4];
    const float* kb   = (const float*)d_in[5];
    const float* vw   = (const float*)d_in[6];
    const float* vb   = (const float*)d_in[7];
    const float* ow   = (const float*)d_in[8];
    const float* ob   = (const float*)d_in[9];
    const float* rk   = (const float*)d_in[10];
    const float* rv   = (const float*)d_in[11];
    const float* ln1g = (const float*)d_in[12];
    const float* ln1b = (const float*)d_in[13];
    const float* w1   = (const float*)d_in[14];
    const float* b1   = (const float*)d_in[15];
    const float* w2   = (const float*)d_in[16];
    const float* b2   = (const float*)d_in[17];
    const float* ln2g = (const float*)d_in[18];
    const float* ln2b = (const float*)d_in[19];

    float *gx,*gt;
    __nv_bfloat16 *gxh,*gxl,*gqh,*gql,*gkh,*gkl,*gvh,*gvl,*goh,*gol,*ghh,*ghl;
    __nv_bfloat16 *wqh,*wql,*wkh,*wkl,*wvh,*wvl,*woh,*wol,*w1h,*w1l,*w2h,*w2l;
    cudaGetSymbolAddress((void**)&gx, g_x);
    cudaGetSymbolAddress((void**)&gt, g_t);
    cudaGetSymbolAddress((void**)&gxh, g_xh); cudaGetSymbolAddress((void**)&gxl, g_xl);
    cudaGetSymbolAddress((void**)&gqh, g_qh); cudaGetSymbolAddress((void**)&gql, g_ql);
    cudaGetSymbolAddress((void**)&gkh, g_kh); cudaGetSymbolAddress((void**)&gkl, g_kl);
    cudaGetSymbolAddress((void**)&gvh, g_vh); cudaGetSymbolAddress((void**)&gvl, g_vl);
    cudaGetSymbolAddress((void**)&goh, g_oh); cudaGetSymbolAddress((void**)&gol, g_ol);
    cudaGetSymbolAddress((void**)&ghh, g_hh); cudaGetSymbolAddress((void**)&ghl, g_hl);
    cudaGetSymbolAddress((void**)&wqh, g_wqh); cudaGetSymbolAddress((void**)&wql, g_wql);
    cudaGetSymbolAddress((void**)&wkh, g_wkh); cudaGetSymbolAddress((void**)&wkl, g_wkl);
    cudaGetSymbolAddress((void**)&wvh, g_wvh); cudaGetSymbolAddress((void**)&wvl, g_wvl);
    cudaGetSymbolAddress((void**)&woh, g_woh); cudaGetSymbolAddress((void**)&wol, g_wol);
    cudaGetSymbolAddress((void**)&w1h, g_w1h); cudaGetSymbolAddress((void**)&w1l, g_w1l);
    cudaGetSymbolAddress((void**)&w2h, g_w2h); cudaGetSymbolAddress((void**)&w2l, g_w2l);

    cudaFuncSetAttribute(attn_mma_kernel, cudaFuncAttributeMaxDynamicSharedMemorySize, ATTN_SMEM_BYTES);

    // prologue: split input + weights once
    {
        int nx = BB*CC*TT;
        split_copy_kernel<<<nx/4/256, 256>>>(x, gx, gxh, gxl, nx);
        int nw = LL*CC*CC;
        split_kernel<<<nw/4/256, 256>>>(qw, wqh, wql, nw);
        split_kernel<<<nw/4/256, 256>>>(kw, wkh, wkl, nw);
        split_kernel<<<nw/4/256, 256>>>(vw, wvh, wvl, nw);
        split_kernel<<<nw/4/256, 256>>>(ow, woh, wol, nw);
        int nf = LL*FF*CC;
        split_kernel<<<nf/4/256, 256>>>(w1, w1h, w1l, nf);
        split_kernel<<<nf/4/256, 256>>>(w2, w2h, w2l, nf);
    }

    const float inv_scale = 0.125f; // 1/sqrt(64)
    dim3 blk(256);
    for (int i=0;i<LL;i++){
        size_t wofs = (size_t)i*CC*CC;
        size_t fofs = (size_t)i*FF*CC;
        // q,k,v projections -> split bf16
        gemm_bf16_kernel<0,0,1,1><<<dim3(TT/128, CC/128, BB), blk>>>(
            wqh+wofs, wql+wofs, gxh, gxl, qb+i*CC, mask, nullptr, gqh, gql, CC, TT, CC, inv_scale);
        gemm_bf16_kernel<0,0,1,0><<<dim3(TT/128, CC/128, BB), blk>>>(
            wkh+wofs, wkl+wofs, gxh, gxl, kb+i*CC, mask, nullptr, gkh, gkl, CC, TT, CC, 1.f);
        gemm_bf16_kernel<0,0,1,0><<<dim3(TT/128, CC/128, BB), blk>>>(
            wvh+wofs, wvl+wofs, gxh, gxl, vb+i*CC, mask, nullptr, gvh, gvl, CC, TT, CC, 1.f);
        // attention -> split bf16 o
        attn_mma_kernel<<<dim3(TT/64, HH, BB), dim3(128), ATTN_SMEM_BYTES>>>(
            gqh, gql, gkh, gkl, gvh, gvl,
            rk + (size_t)i*RNUM*HDD, rv + (size_t)i*RNUM*HDD, mask, goh, gol);
        // o projection -> fp32
        gemm_bf16_kernel<0,0,0,0><<<dim3(TT/128, CC/128, BB), blk>>>(
            woh+wofs, wol+wofs, goh, gol, ob+i*CC, mask, gt, nullptr, nullptr, CC, TT, CC, 1.f);
        // ln1: fp32 unmasked residual, split masked (feeds w1)
        add_ln_kernel<<<dim3(TT/32, BB), blk>>>(gx, gt, ln1g+i*CC, ln1b+i*CC, mask, 0, gx, gxh, gxl);
        // ffn
        gemm_bf16_kernel<1,1,1,0><<<dim3(TT/128, FF/128, BB), blk>>>(
            w1h+fofs, w1l+fofs, gxh, gxl, b1+i*FF, mask, nullptr, ghh, ghl, FF, TT, CC, 1.f);
        gemm_bf16_kernel<0,1,0,0><<<dim3(TT/128, CC/128, BB), blk>>>(
            w2h+fofs, w2l+fofs, ghh, ghl, b2+i*CC, mask, gt, nullptr, nullptr, CC, TT, FF, 1.f);
        // ln2: fp32 masked (residual/next-layer/final), split masked (feeds next q/k/v)
        float* dst = (i==LL-1) ? (float*)d_out : gx;
        add_ln_kernel<<<dim3(TT/32, BB), blk>>>(gx, gt, ln2g+i*CC, ln2b+i*CC, mask, 1, dst, gxh, gxl);
    }
}

// round 5
// speedup vs baseline: 3.5777x; 1.6349x over previous
#include <cuda_runtime.h>
#include <cuda_fp16.h>
#include <math.h>

#define BB 4
#define CC 512
#define TT 1024
#define HH 8
#define HDD 64
#define FF 2048
#define LL 4
#define WW 4
#define RNUM 9

// ---------------- scratch (no allocations allowed) ----------------
__device__ float g_x[BB*CC*TT];          // fp32 residual / layer state
__device__ float g_t[BB*CC*TT];          // fp32 gemm output (pre-LN)
// fp16 activations
__device__ __half g_xf[BB*CC*TT];
__device__ __half g_qf[BB*CC*TT];
__device__ __half g_kf[BB*CC*TT];
__device__ __half g_vf[BB*CC*TT];
__device__ __half g_of[BB*CC*TT];
__device__ __half g_hf[BB*FF*TT];
// fp16 weights (all layers)
__device__ __half g_wq[LL*CC*CC], g_wk[LL*CC*CC], g_wv[LL*CC*CC], g_wo[LL*CC*CC];
__device__ __half g_w1[LL*FF*CC], g_w2[LL*CC*FF];

// ---------------- helpers ----------------
__device__ __forceinline__ void mma16816(float* d, const unsigned* a, const unsigned* b){
    asm volatile("mma.sync.aligned.m16n8k16.row.col.f32.f16.f16.f32 "
        "{%0,%1,%2,%3}, {%4,%5,%6,%7}, {%8,%9}, {%0,%1,%2,%3};"
        : "+f"(d[0]),"+f"(d[1]),"+f"(d[2]),"+f"(d[3])
        : "r"(a[0]),"r"(a[1]),"r"(a[2]),"r"(a[3]), "r"(b[0]),"r"(b[1]));
}
__device__ __forceinline__ void ldsm4(unsigned* r, const void* p){
    unsigned addr = (unsigned)__cvta_generic_to_shared(p);
    asm volatile("ldmatrix.sync.aligned.m8n8.x4.shared.b16 {%0,%1,%2,%3}, [%4];"
        : "=r"(r[0]),"=r"(r[1]),"=r"(r[2]),"=r"(r[3]) : "r"(addr));
}
__device__ __forceinline__ void ldsm4t(unsigned* r, const void* p){
    unsigned addr = (unsigned)__cvta_generic_to_shared(p);
    asm volatile("ldmatrix.sync.aligned.m8n8.x4.trans.shared.b16 {%0,%1,%2,%3}, [%4];"
        : "=r"(r[0]),"=r"(r[1]),"=r"(r[2]),"=r"(r[3]) : "r"(addr));
}
__device__ __forceinline__ void ldsm2t(unsigned* r, const void* p){
    unsigned addr = (unsigned)__cvta_generic_to_shared(p);
    asm volatile("ldmatrix.sync.aligned.m8n8.x2.trans.shared.b16 {%0,%1}, [%2];"
        : "=r"(r[0]),"=r"(r[1]) : "r"(addr));
}
__device__ __forceinline__ unsigned pack_h2(float x, float y){
    __half2 t = __floats2half2_rn(x, y);
    return *(unsigned*)&t;
}
__device__ __forceinline__ void cpa16(void* s, const void* g){
    unsigned sa = (unsigned)__cvta_generic_to_shared(s);
    asm volatile("cp.async.cg.shared.global [%0], [%1], 16;" :: "r"(sa), "l"(g));
}
__device__ __forceinline__ void cpcommit(){ asm volatile("cp.async.commit_group;"); }
template<int NN> __device__ __forceinline__ void cpwait(){ asm volatile("cp.async.wait_group %0;" :: "n"(NN)); }

// ---------------- fp32 -> fp16 convert (prologue) ----------------
__global__ void cvt_kernel(const float* __restrict__ in, __half* __restrict__ o, int n){
    int i = (blockIdx.x*blockDim.x + threadIdx.x)*4;
    if (i >= n) return;
    float4 v = *(const float4*)&in[i];
    __half2 a = __floats2half2_rn(v.x, v.y);
    __half2 b = __floats2half2_rn(v.z, v.w);
    *(__half2*)&o[i]   = a;
    *(__half2*)&o[i+2] = b;
}
__global__ void cvt_copy_kernel(const float* __restrict__ in, float* __restrict__ of,
                                __half* __restrict__ o, int n){
    int i = (blockIdx.x*blockDim.x + threadIdx.x)*4;
    if (i >= n) return;
    float4 v = *(const float4*)&in[i];
    *(float4*)&of[i] = v;
    *(__half2*)&o[i]   = __floats2half2_rn(v.x, v.y);
    *(__half2*)&o[i+2] = __floats2half2_rn(v.z, v.w);
}

// ---------------- fp16 GEMM with cp.async double buffer ----------------
// out[b][m][n] = sum_k A[m][k] B[b][k][n] (+bias, epilogue)
template<int RELU, int MASK_OUT, int F16_OUT, int DO_SCALE>
__global__ void __launch_bounds__(256,2) gemm_f16_kernel(
    const __half* __restrict__ A_g, const __half* __restrict__ B_g,
    const float* __restrict__ bias, const float* __restrict__ mask,
    float* __restrict__ outF, __half* __restrict__ outH,
    int M, int N, int K, float scale)
{
    __shared__ __half As[2][128][40];
    __shared__ __half Bs[2][32][136];

    int b = blockIdx.z;
    const __half* B_b = B_g + (size_t)b*K*N;
    int m0 = blockIdx.y*128, n0 = blockIdx.x*128;
    int tid = threadIdx.x;
    int l = tid & 31, w = tid >> 5;
    int wm0 = (w >> 2) * 64;
    int wn0 = (w & 3) * 32;

    float acc[4][4][4];
    #pragma unroll
    for (int mi=0;mi<4;mi++)
        #pragma unroll
        for (int ni=0;ni<4;ni++)
            #pragma unroll
            for (int e=0;e<4;e++) acc[mi][ni][e]=0.f;

    int nt = K/32;
    auto load_stage = [&](int it, int buf){
        int k0 = it*32;
        #pragma unroll
        for (int p=0;p<2;p++){
            int c = tid + p*256;
            int row = c>>2, col8 = (c&3)*8;
            cpa16(&As[buf][row][col8], A_g + (size_t)(m0+row)*K + k0 + col8);
        }
        #pragma unroll
        for (int p=0;p<2;p++){
            int c = tid + p*256;
            int row = c>>4, col8 = (c&15)*8;
            cpa16(&Bs[buf][row][col8], B_b + (size_t)(k0+row)*N + n0 + col8);
        }
    };

    load_stage(0,0); cpcommit();

    for (int it=0; it<nt; ++it){
        int buf = it & 1;
        if (it+1 < nt){ load_stage(it+1, buf^1); cpcommit(); cpwait<1>(); }
        else cpwait<0>();
        __syncthreads();

        #pragma unroll
        for (int ks=0; ks<32; ks+=16){
            unsigned Bf[4][2];
            #pragma unroll
            for (int ni=0;ni<4;ni++)
                ldsm2t(Bf[ni], &Bs[buf][ks + (l & 15)][wn0 + ni*8]);
            #pragma unroll
            for (int mi=0;mi<4;mi++){
                unsigned Af[4];
                ldsm4(Af, &As[buf][wm0 + mi*16 + (l & 15)][ks + (l >> 4)*8]);
                #pragma unroll
                for (int ni=0;ni<4;ni++)
                    mma16816(acc[mi][ni], Af, Bf[ni]);
            }
        }
        __syncthreads();
    }

    // epilogue
    #pragma unroll
    for (int mi=0;mi<4;mi++){
        int r = m0 + wm0 + mi*16 + (l >> 2);
        float bv0 = bias[r], bv1 = bias[r+8];
        #pragma unroll
        for (int ni=0;ni<4;ni++){
            int cn = n0 + wn0 + ni*8 + (l & 3)*2;
            float m00=1.f, m01=1.f;
            if (MASK_OUT){
                m00 = mask[(size_t)b*TT + cn];
                m01 = mask[(size_t)b*TT + cn + 1];
            }
            float c0 = acc[mi][ni][0] + bv0;
            float c1 = acc[mi][ni][1] + bv0;
            float c2 = acc[mi][ni][2] + bv1;
            float c3 = acc[mi][ni][3] + bv1;
            if (DO_SCALE){ c0*=scale; c1*=scale; c2*=scale; c3*=scale; }
            if (RELU){ c0=fmaxf(c0,0.f); c1=fmaxf(c1,0.f); c2=fmaxf(c2,0.f); c3=fmaxf(c3,0.f); }
            if (MASK_OUT){ c0*=m00; c1*=m01; c2*=m00; c3*=m01; }
            size_t base = (size_t)b*M*N;
            if (F16_OUT){
                *(__half2*)&outH[base + (size_t)r*N + cn]     = __floats2half2_rn(c0,c1);
                *(__half2*)&outH[base + (size_t)(r+8)*N + cn] = __floats2half2_rn(c2,c3);
            } else {
                *(float2*)&outF[base + (size_t)r*N + cn]     = make_float2(c0,c1);
                *(float2*)&outF[base + (size_t)(r+8)*N + cn] = make_float2(c2,c3);
            }
        }
    }
}

// ---------------- tensor-core flash attention, fp16 single-pass ----------------
// grid (T/64, H, B), 128 threads (4 warps). q/k/v/o fp16 in (B,C,T).
#define KQS 72
__global__ void __launch_bounds__(128) attn_mma_kernel(
    const __half* __restrict__ qf, const __half* __restrict__ kf, const __half* __restrict__ vf,
    const float* __restrict__ relk, const float* __restrict__ relv,
    const float* __restrict__ mask, __half* __restrict__ of)
{
    extern __shared__ char smraw[];
    __half* Qf = (__half*)smraw;                      // [64 d][72] (d,i)
    __half* Kf = Qf + 64*KQS;                         // [64 d][72] (d,j)
    __half* Vf = Kf + 64*KQS;                         // [64 d][72] (d,j)
    float* sQRK  = (float*)(Vf + 64*KQS);             // [64 i][9]
    float* sRK   = sQRK + 64*RNUM;                    // [9][64]
    float* sRV   = sRK + RNUM*64;                     // [9][64]
    float* sPB   = sRV + RNUM*64;                     // [64 i][12]
    float* sMask = sPB + 64*12;                       // [64]
    float* sO    = (float*)Kf;                        // [64 d][68] fp32 out stage (overlays K+V)

    int tid = threadIdx.x;
    int l = tid & 31, w = tid >> 5;
    int r = l >> 2;
    int c2 = (l & 3) * 2;
    int i0 = blockIdx.x * 64;
    int h  = blockIdx.y;
    int b  = blockIdx.z;
    const size_t hb = ((size_t)b*CC + h*HDD) * TT;

    // Q tile via cp.async: 64 rows x 128B
    #pragma unroll
    for (int p=0;p<4;p++){
        int c = tid + p*128;
        int row = c>>3, col8 = (c&7)*8;
        cpa16(&Qf[row*KQS + col8], qf + hb + (size_t)row*TT + i0 + col8);
    }
    cpcommit();
    for (int idx = tid; idx < RNUM*64; idx += 128) { sRK[idx] = relk[idx]; sRV[idx] = relv[idx]; }
    cpwait<0>();
    __syncthreads();

    // precompute q . rel_k : [64 i][9]
    for (int idx = tid; idx < 64*RNUM; idx += 128) {
        int ii = idx / RNUM, rr = idx % RNUM;
        float s = 0.f;
        #pragma unroll 8
        for (int d = 0; d < 64; d++)
            s += __half2float(Qf[d*KQS+ii]) * sRK[rr*64 + d];
        sQRK[idx] = s;
    }
    __syncthreads();

    float accO[8][4];
    #pragma unroll
    for (int nb=0;nb<8;nb++)
        #pragma unroll
        for (int e=0;e<4;e++) accO[nb][e]=0.f;
    float mrun0=-1e30f, mrun1=-1e30f, lrun0=0.f, lrun1=0.f;

    for (int jt = 0; jt < TT/64; jt++) {
        int j0t = jt*64;
        #pragma unroll
        for (int p=0;p<4;p++){
            int c = tid + p*128;
            int row = c>>3, col8 = (c&7)*8;
            size_t go = hb + (size_t)row*TT + j0t + col8;
            cpa16(&Kf[row*KQS + col8], kf + go);
            cpa16(&Vf[row*KQS + col8], vf + go);
        }
        cpcommit();
        for (int idx = l; idx < 16*12; idx += 32) sPB[(w*16 + idx/12)*12 + (idx%12)] = 0.f;
        if (tid < 64) sMask[tid] = mask[(size_t)b*TT + j0t + tid];
        cpwait<0>();
        __syncthreads();

        // ---- S = Q K^T (single pass) ----
        float S[8][4];
        #pragma unroll
        for (int nb=0;nb<8;nb++)
            #pragma unroll
            for (int e=0;e<4;e++) S[nb][e]=0.f;
        #pragma unroll
        for (int ks=0; ks<4; ks++){
            int d0 = ks*16;
            unsigned Af[4];
            {
                int row = d0 + ((l>>4)&1)*8 + (l&7);
                int col = w*16 + ((l>>3)&1)*8;
                ldsm4t(Af, &Qf[row*KQS + col]);
            }
            #pragma unroll
            for (int nbp=0; nbp<4; nbp++){
                unsigned Bf[4];
                int row = d0 + ((l>>3)&1)*8 + (l&7);
                int col = nbp*16 + ((l>>4)&1)*8;
                ldsm4t(Bf, &Kf[row*KQS + col]);
                mma16816(S[2*nbp],   Af, &Bf[0]);
                mma16816(S[2*nbp+1], Af, &Bf[2]);
            }
        }

        // ---- rel-k band + mask ----
        #pragma unroll
        for (int nb=0;nb<8;nb++){
            #pragma unroll
            for (int e=0;e<4;e++){
                int iloc = w*16 + r + ((e&2)?8:0);
                int jloc = nb*8 + c2 + (e&1);
                int delta = (j0t + jloc) - (i0 + iloc);
                if (delta >= -WW && delta <= WW) S[nb][e] += sQRK[iloc*RNUM + delta + WW];
                if (sMask[jloc] == 0.f) S[nb][e] = -1e30f;
            }
        }

        // ---- online softmax ----
        float tm0 = -1e30f, tm1 = -1e30f;
        #pragma unroll
        for (int nb=0;nb<8;nb++){
            tm0 = fmaxf(tm0, fmaxf(S[nb][0], S[nb][1]));
            tm1 = fmaxf(tm1, fmaxf(S[nb][2], S[nb][3]));
        }
        tm0 = fmaxf(tm0, __shfl_xor_sync(0xffffffffu, tm0, 1));
        tm0 = fmaxf(tm0, __shfl_xor_sync(0xffffffffu, tm0, 2));
        tm1 = fmaxf(tm1, __shfl_xor_sync(0xffffffffu, tm1, 1));
        tm1 = fmaxf(tm1, __shfl_xor_sync(0xffffffffu, tm1, 2));
        float mn0 = fmaxf(mrun0, tm0), mn1 = fmaxf(mrun1, tm1);
        float co0 = __expf(mrun0 - mn0), co1 = __expf(mrun1 - mn1);
        float rs0 = 0.f, rs1 = 0.f;
        #pragma unroll
        for (int nb=0;nb<8;nb++){
            S[nb][0] = __expf(S[nb][0]-mn0); rs0 += S[nb][0];
            S[nb][1] = __expf(S[nb][1]-mn0); rs0 += S[nb][1];
            S[nb][2] = __expf(S[nb][2]-mn1); rs1 += S[nb][2];
            S[nb][3] = __expf(S[nb][3]-mn1); rs1 += S[nb][3];
        }
        rs0 += __shfl_xor_sync(0xffffffffu, rs0, 1);
        rs0 += __shfl_xor_sync(0xffffffffu, rs0, 2);
        rs1 += __shfl_xor_sync(0xffffffffu, rs1, 1);
        rs1 += __shfl_xor_sync(0xffffffffu, rs1, 2);
        lrun0 = lrun0*co0 + rs0; mrun0 = mn0;
        lrun1 = lrun1*co1 + rs1; mrun1 = mn1;
        #pragma unroll
        for (int nb=0;nb<8;nb++){
            accO[nb][0]*=co0; accO[nb][1]*=co0;
            accO[nb][2]*=co1; accO[nb][3]*=co1;
        }

        // ---- band P -> sPB ----
        #pragma unroll
        for (int nb=0;nb<8;nb++){
            #pragma unroll
            for (int e=0;e<4;e++){
                int iloc = w*16 + r + ((e&2)?8:0);
                int jloc = nb*8 + c2 + (e&1);
                int delta = (j0t + jloc) - (i0 + iloc);
                if (delta >= -WW && delta <= WW) sPB[iloc*12 + delta + WW] = S[nb][e];
            }
        }
        __syncwarp();

        // ---- O += P V (single pass) ----
        #pragma unroll
        for (int s=0; s<4; s++){
            unsigned Pf[4];
            Pf[0] = pack_h2(S[2*s][0],   S[2*s][1]);
            Pf[1] = pack_h2(S[2*s][2],   S[2*s][3]);
            Pf[2] = pack_h2(S[2*s+1][0], S[2*s+1][1]);
            Pf[3] = pack_h2(S[2*s+1][2], S[2*s+1][3]);
            #pragma unroll
            for (int dp=0; dp<4; dp++){
                unsigned Bf[4];
                int row = dp*16 + ((l>>4)&1)*8 + (l&7);
                int col = s*16 + ((l>>3)&1)*8;
                ldsm4(Bf, &Vf[row*KQS + col]);
                mma16816(accO[2*dp],   Pf, &Bf[0]);
                mma16816(accO[2*dp+1], Pf, &Bf[2]);
            }
        }

        // ---- O += P_band * rel_v ----
        {
            int r0i = (w*16 + r)*12, r1i = (w*16 + r + 8)*12;
            #pragma unroll
            for (int t=0; t<RNUM; t++){
                float pb0 = sPB[r0i + t];
                float pb1 = sPB[r1i + t];
                #pragma unroll
                for (int nb=0;nb<8;nb++){
                    int d0 = nb*8 + c2;
                    float rv0 = sRV[t*64 + d0];
                    float rv1 = sRV[t*64 + d0 + 1];
                    accO[nb][0] += pb0*rv0; accO[nb][1] += pb0*rv1;
                    accO[nb][2] += pb1*rv0; accO[nb][3] += pb1*rv1;
                }
            }
        }
        __syncthreads();
    }

    // ---- normalize, stage fp32 [d][i], fp16 write ----
    float inv0 = 1.f / lrun0, inv1 = 1.f / lrun1;
    #pragma unroll
    for (int nb=0;nb<8;nb++){
        #pragma unroll
        for (int e=0;e<4;e++){
            int iloc = w*16 + r + ((e&2)?8:0);
            int d = nb*8 + c2 + (e&1);
            sO[d*68 + iloc] = accO[nb][e] * ((e&2)?inv1:inv0);
        }
    }
    __syncthreads();
    #pragma unroll
    for (int p=0;p<4;p++){
        int c = tid + p*128;
        int row = c>>3, col8 = (c&7)*8;
        size_t go = hb + (size_t)row*TT + i0 + col8;
        #pragma unroll
        for (int j=0;j<8;j+=2){
            float v0 = sO[row*68 + col8 + j];
            float v1 = sO[row*68 + col8 + j + 1];
            *(__half2*)&of[go + j] = __floats2half2_rn(v0, v1);
        }
    }
}

// ---------------- fused residual + LayerNorm; writes fp32 + fp16(masked) ----
__global__ void __launch_bounds__(256) add_ln_kernel(
    const float* __restrict__ res, const float* __restrict__ y,
    const float* __restrict__ g, const float* __restrict__ beta,
    const float* __restrict__ mask, int mask_f32, float* __restrict__ dst,
    __half* __restrict__ dstH)
{
    __shared__ float sS[8][32], sS2[8][32];
    int b  = blockIdx.y;
    int tt = threadIdx.x & 31;
    int cg = threadIdx.x >> 5;
    int t  = blockIdx.x*32 + tt;
    size_t base = (size_t)b*CC*TT + t;
    float s=0.f, s2=0.f;
    for (int c=cg; c<CC; c+=8){
        float vv = res[base + (size_t)c*TT] + y[base + (size_t)c*TT];
        s += vv; s2 += vv*vv;
    }
    sS[cg][tt]=s; sS2[cg][tt]=s2;
    __syncthreads();
    if (cg==0){
        #pragma unroll
        for (int i=1;i<8;i++){ s += sS[i][tt]; s2 += sS2[i][tt]; }
        float mean = s * (1.f/CC);
        float var  = s2 * (1.f/CC) - mean*mean;
        sS[0][tt]  = mean;
        sS2[0][tt] = rsqrtf(var + 1e-6f);
    }
    __syncthreads();
    float mean = sS[0][tt], inv = sS2[0][tt];
    float mk = mask[(size_t)b*TT + t];
    float mkf = mask_f32 ? mk : 1.f;
    for (int c=cg; c<CC; c+=8){
        float vv  = res[base + (size_t)c*TT] + y[base + (size_t)c*TT];
        float ovv = (vv-mean)*inv*g[c] + beta[c];
        dst[base + (size_t)c*TT] = ovv*mkf;
        dstH[base + (size_t)c*TT] = __float2half(ovv*mk);
    }
}

#define ATTN_SMEM_BYTES 40960

extern "C" void kernel_launch(void* const* d_in, const int* in_sizes, int n_in,
                              void* d_out, int out_size)
{
    const float* x    = (const float*)d_in[0];
    const float* mask = (const float*)d_in[1];
    const float* qw   = (const float*)d_in[2];
    const float* qb   = (const float*)d_in[3];
    const float* kw   = (const float*)d_in[4];
    const float* kb   = (const float*)d_in[5];
    const float* vw   = (const float*)d_in[6];
    const float* vb   = (const float*)d_in[7];
    const float* ow   = (const float*)d_in[8];
    const float* ob   = (const float*)d_in[9];
    const float* rk   = (const float*)d_in[10];
    const float* rv   = (const float*)d_in[11];
    const float* ln1g = (const float*)d_in[12];
    const float* ln1b = (const float*)d_in[13];
    const float* w1   = (const float*)d_in[14];
    const float* b1   = (const float*)d_in[15];
    const float* w2   = (const float*)d_in[16];
    const float* b2   = (const float*)d_in[17];
    const float* ln2g = (const float*)d_in[18];
    const float* ln2b = (const float*)d_in[19];

    float *gx,*gt;
    __half *gxf,*gqf,*gkf,*gvf,*gof,*ghf;
    __half *wq,*wk,*wv,*wo,*w1f,*w2f;
    cudaGetSymbolAddress((void**)&gx, g_x);
    cudaGetSymbolAddress((void**)&gt, g_t);
    cudaGetSymbolAddress((void**)&gxf, g_xf);
    cudaGetSymbolAddress((void**)&gqf, g_qf);
    cudaGetSymbolAddress((void**)&gkf, g_kf);
    cudaGetSymbolAddress((void**)&gvf, g_vf);
    cudaGetSymbolAddress((void**)&gof, g_of);
    cudaGetSymbolAddress((void**)&ghf, g_hf);
    cudaGetSymbolAddress((void**)&wq, g_wq);
    cudaGetSymbolAddress((void**)&wk, g_wk);
    cudaGetSymbolAddress((void**)&wv, g_wv);
    cudaGetSymbolAddress((void**)&wo, g_wo);
    cudaGetSymbolAddress((void**)&w1f, g_w1);
    cudaGetSymbolAddress((void**)&w2f, g_w2);

    cudaFuncSetAttribute(attn_mma_kernel, cudaFuncAttributeMaxDynamicSharedMemorySize, ATTN_SMEM_BYTES);

    // prologue: convert input + weights once
    {
        int nx = BB*CC*TT;
        cvt_copy_kernel<<<nx/4/256, 256>>>(x, gx, gxf, nx);
        int nw = LL*CC*CC;
        cvt_kernel<<<nw/4/256, 256>>>(qw, wq, nw);
        cvt_kernel<<<nw/4/256, 256>>>(kw, wk, nw);
        cvt_kernel<<<nw/4/256, 256>>>(vw, wv, nw);
        cvt_kernel<<<nw/4/256, 256>>>(ow, wo, nw);
        int nf = LL*FF*CC;
        cvt_kernel<<<nf/4/256, 256>>>(w1, w1f, nf);
        cvt_kernel<<<nf/4/256, 256>>>(w2, w2f, nf);
    }

    const float inv_scale = 0.125f; // 1/sqrt(64)
    dim3 blk(256);
    for (int i=0;i<LL;i++){
        size_t wofs = (size_t)i*CC*CC;
        size_t fofs = (size_t)i*FF*CC;
        // q,k,v projections -> fp16
        gemm_f16_kernel<0,0,1,1><<<dim3(TT/128, CC/128, BB), blk>>>(
            wq+wofs, gxf, qb+i*CC, mask, nullptr, gqf, CC, TT, CC, inv_scale);
        gemm_f16_kernel<0,0,1,0><<<dim3(TT/128, CC/128, BB), blk>>>(
            wk+wofs, gxf, kb+i*CC, mask, nullptr, gkf, CC, TT, CC, 1.f);
        gemm_f16_kernel<0,0,1,0><<<dim3(TT/128, CC/128, BB), blk>>>(
            wv+wofs, gxf, vb+i*CC, mask, nullptr, gvf, CC, TT, CC, 1.f);
        // attention -> fp16 o
        attn_mma_kernel<<<dim3(TT/64, HH, BB), dim3(128), ATTN_SMEM_BYTES>>>(
            gqf, gkf, gvf, rk + (size_t)i*RNUM*HDD, rv + (size_t)i*RNUM*HDD, mask, gof);
        // o projection -> fp32
        gemm_f16_kernel<0,0,0,0><<<dim3(TT/128, CC/128, BB), blk>>>(
            wo+wofs, gof, ob+i*CC, mask, gt, nullptr, CC, TT, CC, 1.f);
        // ln1: fp32 unmasked residual, fp16 masked (feeds w1)
        add_ln_kernel<<<dim3(TT/32, BB), blk>>>(gx, gt, ln1g+i*CC, ln1b+i*CC, mask, 0, gx, gxf);
        // ffn
        gemm_f16_kernel<1,1,1,0><<<dim3(TT/128, FF/128, BB), blk>>>(
            w1f+fofs, gxf, b1+i*FF, mask, nullptr, ghf, FF, TT, CC, 1.f);
        gemm_f16_kernel<0,1,0,0><<<dim3(TT/128, CC/128, BB), blk>>>(
            w2f+fofs, ghf, b2+i*CC, mask, gt, nullptr, CC, TT, FF, 1.f);
        // ln2: fp32 masked (residual/next-layer/final), fp16 masked (feeds next q/k/v)
        float* dst = (i==LL-1) ? (float*)d_out : gx;
        add_ln_kernel<<<dim3(TT/32, BB), blk>>>(gx, gt, ln2g+i*CC, ln2b+i*CC, mask, 1, dst, gxf);
    }
}

// round 6
// speedup vs baseline: 4.3047x; 1.2032x over previous
#include <cuda_runtime.h>
#include <cuda_fp16.h>
#include <math.h>

#define BB 4
#define CC 512
#define TT 1024
#define HH 8
#define HDD 64
#define FF 2048
#define LL 4
#define WW 4
#define RNUM 9

// ---------------- scratch (no allocations allowed) ----------------
__device__ float g_x[BB*CC*TT];          // fp32 residual / layer state
__device__ float g_t[BB*CC*TT];          // fp32 gemm output (pre-LN)
// fp16 activations
__device__ __half g_xf[BB*CC*TT];
__device__ __half g_qkv[BB*3*CC*TT];     // fused q|k|v per batch
__device__ __half g_of[BB*CC*TT];
__device__ __half g_hf[BB*FF*TT];
// fp16 weights
__device__ __half g_wqkv[LL*3*CC*CC];    // [L][q|k|v][CC][CC]
__device__ float  g_bqkv[LL*3*CC];
__device__ __half g_wo[LL*CC*CC];
__device__ __half g_w1[LL*FF*CC], g_w2[LL*CC*FF];

// ---------------- helpers ----------------
__device__ __forceinline__ void mma16816(float* d, const unsigned* a, const unsigned* b){
    asm volatile("mma.sync.aligned.m16n8k16.row.col.f32.f16.f16.f32 "
        "{%0,%1,%2,%3}, {%4,%5,%6,%7}, {%8,%9}, {%0,%1,%2,%3};"
        : "+f"(d[0]),"+f"(d[1]),"+f"(d[2]),"+f"(d[3])
        : "r"(a[0]),"r"(a[1]),"r"(a[2]),"r"(a[3]), "r"(b[0]),"r"(b[1]));
}
__device__ __forceinline__ void ldsm4(unsigned* r, const void* p){
    unsigned addr = (unsigned)__cvta_generic_to_shared(p);
    asm volatile("ldmatrix.sync.aligned.m8n8.x4.shared.b16 {%0,%1,%2,%3}, [%4];"
        : "=r"(r[0]),"=r"(r[1]),"=r"(r[2]),"=r"(r[3]) : "r"(addr));
}
__device__ __forceinline__ void ldsm4t(unsigned* r, const void* p){
    unsigned addr = (unsigned)__cvta_generic_to_shared(p);
    asm volatile("ldmatrix.sync.aligned.m8n8.x4.trans.shared.b16 {%0,%1,%2,%3}, [%4];"
        : "=r"(r[0]),"=r"(r[1]),"=r"(r[2]),"=r"(r[3]) : "r"(addr));
}
__device__ __forceinline__ void ldsm2t(unsigned* r, const void* p){
    unsigned addr = (unsigned)__cvta_generic_to_shared(p);
    asm volatile("ldmatrix.sync.aligned.m8n8.x2.trans.shared.b16 {%0,%1}, [%2];"
        : "=r"(r[0]),"=r"(r[1]) : "r"(addr));
}
__device__ __forceinline__ unsigned pack_h2(float x, float y){
    __half2 t = __floats2half2_rn(x, y);
    return *(unsigned*)&t;
}
__device__ __forceinline__ void cpa16(void* s, const void* g){
    unsigned sa = (unsigned)__cvta_generic_to_shared(s);
    asm volatile("cp.async.cg.shared.global [%0], [%1], 16;" :: "r"(sa), "l"(g));
}
__device__ __forceinline__ void cpcommit(){ asm volatile("cp.async.commit_group;"); }
template<int NN> __device__ __forceinline__ void cpwait(){ asm volatile("cp.async.wait_group %0;" :: "n"(NN)); }

// ---------------- prologue converts ----------------
__global__ void cvt_kernel(const float* __restrict__ in, __half* __restrict__ o, int n){
    int i = (blockIdx.x*blockDim.x + threadIdx.x)*4;
    if (i >= n) return;
    float4 v = *(const float4*)&in[i];
    *(__half2*)&o[i]   = __floats2half2_rn(v.x, v.y);
    *(__half2*)&o[i+2] = __floats2half2_rn(v.z, v.w);
}
__global__ void cvt_copy_kernel(const float* __restrict__ in, float* __restrict__ of,
                                __half* __restrict__ o, int n){
    int i = (blockIdx.x*blockDim.x + threadIdx.x)*4;
    if (i >= n) return;
    float4 v = *(const float4*)&in[i];
    *(float4*)&of[i] = v;
    *(__half2*)&o[i]   = __floats2half2_rn(v.x, v.y);
    *(__half2*)&o[i+2] = __floats2half2_rn(v.z, v.w);
}
// interleave q,k,v weights -> [L][3][CC][CC]
__global__ void cvt3_kernel(const float* __restrict__ q, const float* __restrict__ k,
                            const float* __restrict__ v, __half* __restrict__ dst){
    const int per = CC*CC;
    int i = (blockIdx.x*blockDim.x + threadIdx.x)*4;
    if (i >= LL*3*per) return;
    int layer = i/(3*per); int rem = i - layer*3*per; int sel = rem/per; int off = rem - sel*per;
    const float* s = sel==0 ? q : (sel==1 ? k : v);
    float4 vv = *(const float4*)&s[layer*per + off];
    *(__half2*)&dst[i]   = __floats2half2_rn(vv.x, vv.y);
    *(__half2*)&dst[i+2] = __floats2half2_rn(vv.z, vv.w);
}
__global__ void cat_bias_kernel(const float* __restrict__ qb, const float* __restrict__ kb,
                                const float* __restrict__ vb, float* __restrict__ dst){
    int i = blockIdx.x*blockDim.x + threadIdx.x;
    if (i >= LL*3*CC) return;
    int layer = i/(3*CC); int rem = i - layer*3*CC; int sel = rem/CC; int off = rem - sel*CC;
    const float* s = sel==0 ? qb : (sel==1 ? kb : vb);
    dst[i] = s[layer*CC + off];
}

// ---------------- fp16 GEMM with cp.async double buffer ----------------
// out[b][m][n] = sum_k A[m][k] B[b][k][n] (+bias, epilogue). rows < scaleM get *scale.
template<int RELU, int MASK_OUT, int F16_OUT, int DO_SCALE>
__global__ void __launch_bounds__(256,2) gemm_f16_kernel(
    const __half* __restrict__ A_g, const __half* __restrict__ B_g,
    const float* __restrict__ bias, const float* __restrict__ mask,
    float* __restrict__ outF, __half* __restrict__ outH,
    int M, int N, int K, float scale, int scaleM)
{
    __shared__ __half As[2][128][40];
    __shared__ __half Bs[2][32][136];

    int b = blockIdx.z;
    const __half* B_b = B_g + (size_t)b*K*N;
    int m0 = blockIdx.y*128, n0 = blockIdx.x*128;
    int tid = threadIdx.x;
    int l = tid & 31, w = tid >> 5;
    int wm0 = (w >> 2) * 64;
    int wn0 = (w & 3) * 32;

    float acc[4][4][4];
    #pragma unroll
    for (int mi=0;mi<4;mi++)
        #pragma unroll
        for (int ni=0;ni<4;ni++)
            #pragma unroll
            for (int e=0;e<4;e++) acc[mi][ni][e]=0.f;

    int nt = K/32;
    auto load_stage = [&](int it, int buf){
        int k0 = it*32;
        #pragma unroll
        for (int p=0;p<2;p++){
            int c = tid + p*256;
            int row = c>>2, col8 = (c&3)*8;
            cpa16(&As[buf][row][col8], A_g + (size_t)(m0+row)*K + k0 + col8);
        }
        #pragma unroll
        for (int p=0;p<2;p++){
            int c = tid + p*256;
            int row = c>>4, col8 = (c&15)*8;
            cpa16(&Bs[buf][row][col8], B_b + (size_t)(k0+row)*N + n0 + col8);
        }
    };

    load_stage(0,0); cpcommit();

    for (int it=0; it<nt; ++it){
        int buf = it & 1;
        if (it+1 < nt){ load_stage(it+1, buf^1); cpcommit(); cpwait<1>(); }
        else cpwait<0>();
        __syncthreads();

        #pragma unroll
        for (int ks=0; ks<32; ks+=16){
            unsigned Bf[4][2];
            #pragma unroll
            for (int ni=0;ni<4;ni++)
                ldsm2t(Bf[ni], &Bs[buf][ks + (l & 15)][wn0 + ni*8]);
            #pragma unroll
            for (int mi=0;mi<4;mi++){
                unsigned Af[4];
                ldsm4(Af, &As[buf][wm0 + mi*16 + (l & 15)][ks + (l >> 4)*8]);
                #pragma unroll
                for (int ni=0;ni<4;ni++)
                    mma16816(acc[mi][ni], Af, Bf[ni]);
            }
        }
        __syncthreads();
    }

    // epilogue
    float tsc = (DO_SCALE && m0 < scaleM) ? scale : 1.f;
    #pragma unroll
    for (int mi=0;mi<4;mi++){
        int r = m0 + wm0 + mi*16 + (l >> 2);
        float bv0 = bias[r], bv1 = bias[r+8];
        #pragma unroll
        for (int ni=0;ni<4;ni++){
            int cn = n0 + wn0 + ni*8 + (l & 3)*2;
            float m00=1.f, m01=1.f;
            if (MASK_OUT){
                m00 = mask[(size_t)b*TT + cn];
                m01 = mask[(size_t)b*TT + cn + 1];
            }
            float c0 = acc[mi][ni][0] + bv0;
            float c1 = acc[mi][ni][1] + bv0;
            float c2 = acc[mi][ni][2] + bv1;
            float c3 = acc[mi][ni][3] + bv1;
            if (DO_SCALE){ c0*=tsc; c1*=tsc; c2*=tsc; c3*=tsc; }
            if (RELU){ c0=fmaxf(c0,0.f); c1=fmaxf(c1,0.f); c2=fmaxf(c2,0.f); c3=fmaxf(c3,0.f); }
            if (MASK_OUT){ c0*=m00; c1*=m01; c2*=m00; c3*=m01; }
            size_t base = (size_t)b*M*N;
            if (F16_OUT){
                *(__half2*)&outH[base + (size_t)r*N + cn]     = __floats2half2_rn(c0,c1);
                *(__half2*)&outH[base + (size_t)(r+8)*N + cn] = __floats2half2_rn(c2,c3);
            } else {
                *(float2*)&outF[base + (size_t)r*N + cn]     = make_float2(c0,c1);
                *(float2*)&outF[base + (size_t)(r+8)*N + cn] = make_float2(c2,c3);
            }
        }
    }
}

// ---------------- tensor-core flash attention, fp16, double-buffered K/V ----------------
// grid (T/64, H, B), 128 threads (4 warps). qkv fused [b][3C][T]; o fp16 [b][C][T].
#define KQS 72
#define NJT (TT/64)
__global__ void __launch_bounds__(128) attn_mma_kernel(
    const __half* __restrict__ qkv,
    const float* __restrict__ relk, const float* __restrict__ relv,
    const float* __restrict__ mask, __half* __restrict__ of)
{
    extern __shared__ char smraw[];
    __half* Qf = (__half*)smraw;                      // [64 d][72]
    __half* Kf = Qf + 64*KQS;                         // [2][64 d][72]
    __half* Vf = Kf + 2*64*KQS;                       // [2][64 d][72]
    float* sQRK  = (float*)(Vf + 2*64*KQS);           // [64 i][9]
    float* sRK   = sQRK + 64*RNUM;                    // [9][64]
    float* sRV   = sRK + RNUM*64;                     // [9][64]
    float* sPB   = sRV + RNUM*64;                     // [64 i][12]
    float* sMask = sPB + 64*12;                       // [2][64]
    float* sO    = (float*)Kf;                        // [64 d][68] fp32 out stage (overlays K)

    int tid = threadIdx.x;
    int l = tid & 31, w = tid >> 5;
    int r = l >> 2;
    int c2 = (l & 3) * 2;
    int i0 = blockIdx.x * 64;
    int h  = blockIdx.y;
    int b  = blockIdx.z;
    const size_t hbq = ((size_t)b*3*CC + h*HDD) * TT;
    const size_t hbk = hbq + (size_t)CC*TT;
    const size_t hbv = hbq + (size_t)2*CC*TT;
    const size_t hbo = ((size_t)b*CC + h*HDD) * TT;

    auto load_kv = [&](int jt, int buf){
        int j0t = jt*64;
        #pragma unroll
        for (int p=0;p<4;p++){
            int c = tid + p*128;
            int row = c>>3, col8 = (c&7)*8;
            size_t go = (size_t)row*TT + j0t + col8;
            cpa16(&Kf[buf*64*KQS + row*KQS + col8], qkv + hbk + go);
            cpa16(&Vf[buf*64*KQS + row*KQS + col8], qkv + hbv + go);
        }
    };

    // Q tile
    #pragma unroll
    for (int p=0;p<4;p++){
        int c = tid + p*128;
        int row = c>>3, col8 = (c&7)*8;
        cpa16(&Qf[row*KQS + col8], qkv + hbq + (size_t)row*TT + i0 + col8);
    }
    cpcommit();
    load_kv(0,0); cpcommit();
    for (int idx = tid; idx < RNUM*64; idx += 128) { sRK[idx] = relk[idx]; sRV[idx] = relv[idx]; }
    cpwait<1>();   // Q arrived (K0 may still be in flight)
    __syncthreads();

    // precompute q . rel_k : [64 i][9]
    for (int idx = tid; idx < 64*RNUM; idx += 128) {
        int ii = idx / RNUM, rr = idx % RNUM;
        float s = 0.f;
        #pragma unroll 8
        for (int d = 0; d < 64; d++)
            s += __half2float(Qf[d*KQS+ii]) * sRK[rr*64 + d];
        sQRK[idx] = s;
    }
    __syncthreads();

    float accO[8][4];
    #pragma unroll
    for (int nb=0;nb<8;nb++)
        #pragma unroll
        for (int e=0;e<4;e++) accO[nb][e]=0.f;
    float mrun0=-1e30f, mrun1=-1e30f, lrun0=0.f, lrun1=0.f;

    for (int jt = 0; jt < NJT; jt++) {
        int j0t = jt*64;
        int buf = jt & 1;
        if (jt+1 < NJT){ load_kv(jt+1, buf^1); cpcommit(); }
        for (int idx = l; idx < 16*12; idx += 32) sPB[(w*16 + idx/12)*12 + (idx%12)] = 0.f;
        if (tid < 64) sMask[buf*64 + tid] = mask[(size_t)b*TT + j0t + tid];
        if (jt+1 < NJT) cpwait<1>(); else cpwait<0>();
        __syncthreads();

        const __half* Kb = Kf + buf*64*KQS;
        const __half* Vb = Vf + buf*64*KQS;
        const float* mk = sMask + buf*64;

        // ---- S = Q K^T ----
        float S[8][4];
        #pragma unroll
        for (int nb=0;nb<8;nb++)
            #pragma unroll
            for (int e=0;e<4;e++) S[nb][e]=0.f;
        #pragma unroll
        for (int ks=0; ks<4; ks++){
            int d0 = ks*16;
            unsigned Af[4];
            {
                int row = d0 + ((l>>4)&1)*8 + (l&7);
                int col = w*16 + ((l>>3)&1)*8;
                ldsm4t(Af, &Qf[row*KQS + col]);
            }
            #pragma unroll
            for (int nbp=0; nbp<4; nbp++){
                unsigned Bf[4];
                int row = d0 + ((l>>3)&1)*8 + (l&7);
                int col = nbp*16 + ((l>>4)&1)*8;
                ldsm4t(Bf, &Kb[row*KQS + col]);
                mma16816(S[2*nbp],   Af, &Bf[0]);
                mma16816(S[2*nbp+1], Af, &Bf[2]);
            }
        }

        // ---- rel-k band + mask ----
        #pragma unroll
        for (int nb=0;nb<8;nb++){
            #pragma unroll
            for (int e=0;e<4;e++){
                int iloc = w*16 + r + ((e&2)?8:0);
                int jloc = nb*8 + c2 + (e&1);
                int delta = (j0t + jloc) - (i0 + iloc);
                if (delta >= -WW && delta <= WW) S[nb][e] += sQRK[iloc*RNUM + delta + WW];
                if (mk[jloc] == 0.f) S[nb][e] = -1e30f;
            }
        }

        // ---- online softmax ----
        float tm0 = -1e30f, tm1 = -1e30f;
        #pragma unroll
        for (int nb=0;nb<8;nb++){
            tm0 = fmaxf(tm0, fmaxf(S[nb][0], S[nb][1]));
            tm1 = fmaxf(tm1, fmaxf(S[nb][2], S[nb][3]));
        }
        tm0 = fmaxf(tm0, __shfl_xor_sync(0xffffffffu, tm0, 1));
        tm0 = fmaxf(tm0, __shfl_xor_sync(0xffffffffu, tm0, 2));
        tm1 = fmaxf(tm1, __shfl_xor_sync(0xffffffffu, tm1, 1));
        tm1 = fmaxf(tm1, __shfl_xor_sync(0xffffffffu, tm1, 2));
        float mn0 = fmaxf(mrun0, tm0), mn1 = fmaxf(mrun1, tm1);
        float co0 = __expf(mrun0 - mn0), co1 = __expf(mrun1 - mn1);
        float rs0 = 0.f, rs1 = 0.f;
        #pragma unroll
        for (int nb=0;nb<8;nb++){
            S[nb][0] = __expf(S[nb][0]-mn0); rs0 += S[nb][0];
            S[nb][1] = __expf(S[nb][1]-mn0); rs0 += S[nb][1];
            S[nb][2] = __expf(S[nb][2]-mn1); rs1 += S[nb][2];
            S[nb][3] = __expf(S[nb][3]-mn1); rs1 += S[nb][3];
        }
        rs0 += __shfl_xor_sync(0xffffffffu, rs0, 1);
        rs0 += __shfl_xor_sync(0xffffffffu, rs0, 2);
        rs1 += __shfl_xor_sync(0xffffffffu, rs1, 1);
        rs1 += __shfl_xor_sync(0xffffffffu, rs1, 2);
        lrun0 = lrun0*co0 + rs0; mrun0 = mn0;
        lrun1 = lrun1*co1 + rs1; mrun1 = mn1;
        #pragma unroll
        for (int nb=0;nb<8;nb++){
            accO[nb][0]*=co0; accO[nb][1]*=co0;
            accO[nb][2]*=co1; accO[nb][3]*=co1;
        }

        // ---- band P -> sPB ----
        #pragma unroll
        for (int nb=0;nb<8;nb++){
            #pragma unroll
            for (int e=0;e<4;e++){
                int iloc = w*16 + r + ((e&2)?8:0);
                int jloc = nb*8 + c2 + (e&1);
                int delta = (j0t + jloc) - (i0 + iloc);
                if (delta >= -WW && delta <= WW) sPB[iloc*12 + delta + WW] = S[nb][e];
            }
        }
        __syncwarp();

        // ---- O += P V ----
        #pragma unroll
        for (int s=0; s<4; s++){
            unsigned Pf[4];
            Pf[0] = pack_h2(S[2*s][0],   S[2*s][1]);
            Pf[1] = pack_h2(S[2*s][2],   S[2*s][3]);
            Pf[2] = pack_h2(S[2*s+1][0], S[2*s+1][1]);
            Pf[3] = pack_h2(S[2*s+1][2], S[2*s+1][3]);
            #pragma unroll
            for (int dp=0; dp<4; dp++){
                unsigned Bf[4];
                int row = dp*16 + ((l>>4)&1)*8 + (l&7);
                int col = s*16 + ((l>>3)&1)*8;
                ldsm4(Bf, &Vb[row*KQS + col]);
                mma16816(accO[2*dp],   Pf, &Bf[0]);
                mma16816(accO[2*dp+1], Pf, &Bf[2]);
            }
        }

        // ---- O += P_band * rel_v ----
        {
            int r0i = (w*16 + r)*12, r1i = (w*16 + r + 8)*12;
            #pragma unroll
            for (int t=0; t<RNUM; t++){
                float pb0 = sPB[r0i + t];
                float pb1 = sPB[r1i + t];
                #pragma unroll
                for (int nb=0;nb<8;nb++){
                    int d0 = nb*8 + c2;
                    float rv0 = sRV[t*64 + d0];
                    float rv1 = sRV[t*64 + d0 + 1];
                    accO[nb][0] += pb0*rv0; accO[nb][1] += pb0*rv1;
                    accO[nb][2] += pb1*rv0; accO[nb][3] += pb1*rv1;
                }
            }
        }
        __syncthreads();
    }

    // ---- normalize, stage fp32 [d][i], fp16 write ----
    float inv0 = 1.f / lrun0, inv1 = 1.f / lrun1;
    #pragma unroll
    for (int nb=0;nb<8;nb++){
        #pragma unroll
        for (int e=0;e<4;e++){
            int iloc = w*16 + r + ((e&2)?8:0);
            int d = nb*8 + c2 + (e&1);
            sO[d*68 + iloc] = accO[nb][e] * ((e&2)?inv1:inv0);
        }
    }
    __syncthreads();
    #pragma unroll
    for (int p=0;p<4;p++){
        int c = tid + p*128;
        int row = c>>3, col8 = (c&7)*8;
        size_t go = hbo + (size_t)row*TT + i0 + col8;
        #pragma unroll
        for (int j=0;j<8;j+=2){
            float v0 = sO[row*68 + col8 + j];
            float v1 = sO[row*68 + col8 + j + 1];
            *(__half2*)&of[go + j] = __floats2half2_rn(v0, v1);
        }
    }
}

// ---------------- fused residual + LayerNorm; writes fp32 + fp16(masked) ----
__global__ void __launch_bounds__(256) add_ln_kernel(
    const float* __restrict__ res, const float* __restrict__ y,
    const float* __restrict__ g, const float* __restrict__ beta,
    const float* __restrict__ mask, int mask_f32, float* __restrict__ dst,
    __half* __restrict__ dstH)
{
    __shared__ float sS[8][32], sS2[8][32];
    int b  = blockIdx.y;
    int tt = threadIdx.x & 31;
    int cg = threadIdx.x >> 5;
    int t  = blockIdx.x*32 + tt;
    size_t base = (size_t)b*CC*TT + t;
    float s=0.f, s2=0.f;
    for (int c=cg; c<CC; c+=8){
        float vv = res[base + (size_t)c*TT] + y[base + (size_t)c*TT];
        s += vv; s2 += vv*vv;
    }
    sS[cg][tt]=s; sS2[cg][tt]=s2;
    __syncthreads();
    if (cg==0){
        #pragma unroll
        for (int i=1;i<8;i++){ s += sS[i][tt]; s2 += sS2[i][tt]; }
        float mean = s * (1.f/CC);
        float var  = s2 * (1.f/CC) - mean*mean;
        sS[0][tt]  = mean;
        sS2[0][tt] = rsqrtf(var + 1e-6f);
    }
    __syncthreads();
    float mean = sS[0][tt], inv = sS2[0][tt];
    float mk = mask[(size_t)b*TT + t];
    float mkf = mask_f32 ? mk : 1.f;
    for (int c=cg; c<CC; c+=8){
        float vv  = res[base + (size_t)c*TT] + y[base + (size_t)c*TT];
        float ovv = (vv-mean)*inv*g[c] + beta[c];
        dst[base + (size_t)c*TT] = ovv*mkf;
        dstH[base + (size_t)c*TT] = __float2half(ovv*mk);
    }
}

#define ATTN_SMEM_BYTES 57344

extern "C" void kernel_launch(void* const* d_in, const int* in_sizes, int n_in,
                              void* d_out, int out_size)
{
    const float* x    = (const float*)d_in[0];
    const float* mask = (const float*)d_in[1];
    const float* qw   = (const float*)d_in[2];
    const float* qb   = (const float*)d_in[3];
    const float* kw   = (const float*)d_in[4];
    const float* kb   = (const float*)d_in[5];
    const float* vw   = (const float*)d_in[6];
    const float* vb   = (const float*)d_in[7];
    const float* ow   = (const float*)d_in[8];
    const float* ob   = (const float*)d_in[9];
    const float* rk   = (const float*)d_in[10];
    const float* rv   = (const float*)d_in[11];
    const float* ln1g = (const float*)d_in[12];
    const float* ln1b = (const float*)d_in[13];
    const float* w1   = (const float*)d_in[14];
    const float* b1   = (const float*)d_in[15];
    const float* w2   = (const float*)d_in[16];
    const float* b2   = (const float*)d_in[17];
    const float* ln2g = (const float*)d_in[18];
    const float* ln2b = (const float*)d_in[19];

    float *gx,*gt,*bqkv;
    __half *gxf,*gqkv,*gof,*ghf;
    __half *wqkv,*wo,*w1f,*w2f;
    cudaGetSymbolAddress((void**)&gx, g_x);
    cudaGetSymbolAddress((void**)&gt, g_t);
    cudaGetSymbolAddress((void**)&gxf, g_xf);
    cudaGetSymbolAddress((void**)&gqkv, g_qkv);
    cudaGetSymbolAddress((void**)&gof, g_of);
    cudaGetSymbolAddress((void**)&ghf, g_hf);
    cudaGetSymbolAddress((void**)&wqkv, g_wqkv);
    cudaGetSymbolAddress((void**)&bqkv, g_bqkv);
    cudaGetSymbolAddress((void**)&wo, g_wo);
    cudaGetSymbolAddress((void**)&w1f, g_w1);
    cudaGetSymbolAddress((void**)&w2f, g_w2);

    cudaFuncSetAttribute(attn_mma_kernel, cudaFuncAttributeMaxDynamicSharedMemorySize, ATTN_SMEM_BYTES);

    // prologue: convert input + weights once
    {
        int nx = BB*CC*TT;
        cvt_copy_kernel<<<nx/4/256, 256>>>(x, gx, gxf, nx);
        cvt3_kernel<<<(LL*3*CC*CC)/4/256, 256>>>(qw, kw, vw, wqkv);
        cat_bias_kernel<<<(LL*3*CC + 255)/256, 256>>>(qb, kb, vb, bqkv);
        int nw = LL*CC*CC;
        cvt_kernel<<<nw/4/256, 256>>>(ow, wo, nw);
        int nf = LL*FF*CC;
        cvt_kernel<<<nf/4/256, 256>>>(w1, w1f, nf);
        cvt_kernel<<<nf/4/256, 256>>>(w2, w2f, nf);
    }

    const float inv_scale = 0.125f; // 1/sqrt(64)
    dim3 blk(256);
    for (int i=0;i<LL;i++){
        size_t wofs = (size_t)i*CC*CC;
        size_t fofs = (size_t)i*FF*CC;
        // fused q|k|v projection -> fp16 [b][3C][T]; rows<CC (=q) scaled
        gemm_f16_kernel<0,0,1,1><<<dim3(TT/128, 3*CC/128, BB), blk>>>(
            wqkv + (size_t)i*3*CC*CC, gxf, bqkv + i*3*CC, mask, nullptr, gqkv,
            3*CC, TT, CC, inv_scale, CC);
        // attention -> fp16 o
        attn_mma_kernel<<<dim3(TT/64, HH, BB), dim3(128), ATTN_SMEM_BYTES>>>(
            gqkv, rk + (size_t)i*RNUM*HDD, rv + (size_t)i*RNUM*HDD, mask, gof);
        // o projection -> fp32
        gemm_f16_kernel<0,0,0,0><<<dim3(TT/128, CC/128, BB), blk>>>(
            wo+wofs, gof, ob+i*CC, mask, gt, nullptr, CC, TT, CC, 1.f, 0);
        // ln1: fp32 unmasked residual, fp16 masked (feeds w1)
        add_ln_kernel<<<dim3(TT/32, BB), blk>>>(gx, gt, ln1g+i*CC, ln1b+i*CC, mask, 0, gx, gxf);
        // ffn
        gemm_f16_kernel<1,1,1,0><<<dim3(TT/128, FF/128, BB), blk>>>(
            w1f+fofs, gxf, b1+i*FF, mask, nullptr, ghf, FF, TT, CC, 1.f, 0);
        gemm_f16_kernel<0,1,0,0><<<dim3(TT/128, CC/128, BB), blk>>>(
            w2f+fofs, ghf, b2+i*CC, mask, gt, nullptr, CC, TT, FF, 1.f, 0);
        // ln2: fp32 masked (residual/next-layer/final), fp16 masked (feeds next q/k/v)
        float* dst = (i==LL-1) ? (float*)d_out : gx;
        add_ln_kernel<<<dim3(TT/32, BB), blk>>>(gx, gt, ln2g+i*CC, ln2b+i*CC, mask, 1, dst, gxf);
    }
}